// round 3
// baseline (speedup 1.0000x reference)
#include <cuda_runtime.h>
#include <cstdint>

#define BB 4
#define NN 1024
#define HH 8
#define DD 256
#define LL 4
#define MTOT (BB * NN)  // 4096

// ---------------- scratch buffers (static __device__, no allocation) ----------------
__device__ float g_h[MTOT * DD];
__device__ float g_q[MTOT * DD];
__device__ float g_k[MTOT * DD];
__device__ float g_v[MTOT * DD];
__device__ float g_o[MTOT * DD];
__device__ float g_y[MTOT * DD];
__device__ float g_f[MTOT * DD];

// ============================================================================
// embed: h[b,n,:] = x + in_deg_emb[in_deg[n]] + out_deg_emb[out_deg[n]]
//                     + pos[n,:] @ W_svd + b_svd,  pos = concat(u, -v)
// ============================================================================
__global__ void __launch_bounds__(256) embed_kernel(
    const float* __restrict__ x, const int* __restrict__ ind,
    const int* __restrict__ outd, const float* __restrict__ svd,
    const float* __restrict__ Wsvd, const float* __restrict__ bsvd,
    const float* __restrict__ ide, const float* __restrict__ ode,
    float* __restrict__ h)
{
    int bn = blockIdx.x;            // 0..4095
    int n  = bn & (NN - 1);
    int d  = threadIdx.x;           // 0..255
    __shared__ float pos[32];
    if (d < 32) {
        float v = svd[n * 32 + d];
        pos[d] = (d < 16) ? v : -v;
    }
    __syncthreads();
    int di = ind[n], dо = outd[n];
    float acc = x[(size_t)bn * DD + d]
              + ide[(size_t)di * DD + d]
              + ode[(size_t)dо * DD + d]
              + bsvd[d];
#pragma unroll
    for (int k = 0; k < 32; k++)
        acc = fmaf(pos[k], Wsvd[k * DD + d], acc);
    h[(size_t)bn * DD + d] = acc;
}

// ============================================================================
// GEMM: Y[M=4096, 256] = X[4096,256] @ W[256,256] + bias (+res) (+relu)
// Tiles 64x64x16, 256 threads, 4x4 micro-tile per thread.
// EPI: 0 = bias, 1 = bias+relu, 2 = bias+residual
// ============================================================================
template <int EPI>
__global__ void __launch_bounds__(256) gemm_kernel(
    const float* __restrict__ X, const float* __restrict__ W,
    const float* __restrict__ bias, const float* __restrict__ res,
    float* __restrict__ Y)
{
    __shared__ __align__(16) float As[16][68];   // As[k][m] (transposed X tile)
    __shared__ __align__(16) float Bs[16][64];   // Bs[k][n]
    const int tid = threadIdx.x;
    const int tx = tid & 15, ty = tid >> 4;
    const int m0 = blockIdx.y << 6, n0 = blockIdx.x << 6;

    const int lr = tid >> 2;            // 0..63
    const int lc = (tid & 3) << 2;      // 0,4,8,12
    const int wr = tid >> 4;            // 0..15
    const int wc = (tid & 15) << 2;     // 0..60

    float acc[4][4] = {};

    for (int k0 = 0; k0 < DD; k0 += 16) {
        float4 xa = *(const float4*)&X[(size_t)(m0 + lr) * DD + k0 + lc];
        As[lc + 0][lr] = xa.x;
        As[lc + 1][lr] = xa.y;
        As[lc + 2][lr] = xa.z;
        As[lc + 3][lr] = xa.w;
        *(float4*)&Bs[wr][wc] = *(const float4*)&W[(size_t)(k0 + wr) * DD + n0 + wc];
        __syncthreads();
#pragma unroll
        for (int kk = 0; kk < 16; kk++) {
            const float4 a4 = *(const float4*)&As[kk][ty << 2];
            const float4 b4 = *(const float4*)&Bs[kk][tx << 2];
            const float a[4] = {a4.x, a4.y, a4.z, a4.w};
            const float b[4] = {b4.x, b4.y, b4.z, b4.w};
#pragma unroll
            for (int i = 0; i < 4; i++)
#pragma unroll
                for (int j = 0; j < 4; j++)
                    acc[i][j] = fmaf(a[i], b[j], acc[i][j]);
        }
        __syncthreads();
    }

    const float4 bb = *(const float4*)&bias[n0 + (tx << 2)];
#pragma unroll
    for (int i = 0; i < 4; i++) {
        const int row = m0 + (ty << 2) + i;
        float4 o;
        o.x = acc[i][0] + bb.x;
        o.y = acc[i][1] + bb.y;
        o.z = acc[i][2] + bb.z;
        o.w = acc[i][3] + bb.w;
        if (EPI == 2) {
            const float4 r4 = *(const float4*)&res[(size_t)row * DD + n0 + (tx << 2)];
            o.x += r4.x; o.y += r4.y; o.z += r4.z; o.w += r4.w;
        }
        if (EPI == 1) {
            o.x = fmaxf(o.x, 0.f); o.y = fmaxf(o.y, 0.f);
            o.z = fmaxf(o.z, 0.f); o.w = fmaxf(o.w, 0.f);
        }
        *(float4*)&Y[(size_t)row * DD + n0 + (tx << 2)] = o;
    }
}

// ============================================================================
// Flash attention: per (b,h), QT=64 query tile, KT=64 key tiles, online softmax.
// Bias gathered on the fly: spatial_emb[spatial_pos[q,k] * H + h].
// Warp w owns query rows w*8..w*8+7; lane owns dk = lane (DK=32).
// ============================================================================
__global__ void __launch_bounds__(256) attn_kernel(
    const float* __restrict__ Q, const float* __restrict__ K,
    const float* __restrict__ V, const int* __restrict__ spp,
    const float* __restrict__ spe, float* __restrict__ O)
{
    __shared__ __align__(16) float Qst[32][68];   // [dk][q]
    __shared__ __align__(16) float Kst[32][68];   // [dk][k]
    __shared__ __align__(16) float Vs[64][36];    // [k][dk]
    __shared__ __align__(16) float Ss[64][64];    // [q][k]

    const int tid  = threadIdx.x;
    const int lane = tid & 31, warp = tid >> 5;
    const int tx = tid & 15, ty = tid >> 4;
    const int bh = blockIdx.y;
    const int b  = bh >> 3, h = bh & 7;
    const int q0 = blockIdx.x << 6;
    const float scale = 0.17677669529663687f;   // 1/sqrt(32)

    // load Q tile (transposed to [dk][q])
#pragma unroll
    for (int i = tid; i < 512; i += 256) {
        const int r = i >> 3, c = (i & 7) << 2;
        const float4 v4 = *(const float4*)&Q[(((size_t)b * NN + q0 + r) << 8) + (h << 5) + c];
        Qst[c + 0][r] = v4.x; Qst[c + 1][r] = v4.y;
        Qst[c + 2][r] = v4.z; Qst[c + 3][r] = v4.w;
    }

    float m_i[8], l_i[8], o_i[8];
#pragma unroll
    for (int qq = 0; qq < 8; qq++) { m_i[qq] = -1e30f; l_i[qq] = 0.f; o_i[qq] = 0.f; }

    for (int k0 = 0; k0 < NN; k0 += 64) {
        __syncthreads();   // previous iteration's PV / S use done
#pragma unroll
        for (int i = tid; i < 512; i += 256) {
            const int r = i >> 3, c = (i & 7) << 2;
            const size_t base = (((size_t)b * NN + k0 + r) << 8) + (h << 5) + c;
            const float4 kv = *(const float4*)&K[base];
            Kst[c + 0][r] = kv.x; Kst[c + 1][r] = kv.y;
            Kst[c + 2][r] = kv.z; Kst[c + 3][r] = kv.w;
            *(float4*)&Vs[r][c] = *(const float4*)&V[base];
        }
        __syncthreads();

        // S = Q K^T  (64x64x32)
        float acc[4][4] = {};
#pragma unroll
        for (int kk = 0; kk < 32; kk++) {
            const float4 a4 = *(const float4*)&Qst[kk][ty << 2];
            const float4 b4 = *(const float4*)&Kst[kk][tx << 2];
            const float a[4] = {a4.x, a4.y, a4.z, a4.w};
            const float bq[4] = {b4.x, b4.y, b4.z, b4.w};
#pragma unroll
            for (int i = 0; i < 4; i++)
#pragma unroll
                for (int j = 0; j < 4; j++)
                    acc[i][j] = fmaf(a[i], bq[j], acc[i][j]);
        }

        // scale + spatial bias, store S tile
#pragma unroll
        for (int i = 0; i < 4; i++) {
            const int qg = q0 + (ty << 2) + i;
            const int4 sp4 = *(const int4*)&spp[(size_t)qg * NN + k0 + (tx << 2)];
            float4 s4;
            s4.x = fmaf(acc[i][0], scale, spe[sp4.x * HH + h]);
            s4.y = fmaf(acc[i][1], scale, spe[sp4.y * HH + h]);
            s4.z = fmaf(acc[i][2], scale, spe[sp4.z * HH + h]);
            s4.w = fmaf(acc[i][3], scale, spe[sp4.w * HH + h]);
            *(float4*)&Ss[(ty << 2) + i][tx << 2] = s4;
        }
        __syncthreads();

        // online softmax for my 8 rows
#pragma unroll
        for (int qq = 0; qq < 8; qq++) {
            const int r = (warp << 3) + qq;
            const float x1 = Ss[r][lane];
            const float x2 = Ss[r][lane + 32];
            float mx = fmaxf(x1, x2);
#pragma unroll
            for (int off = 16; off; off >>= 1)
                mx = fmaxf(mx, __shfl_xor_sync(0xffffffffu, mx, off));
            const float mnew = fmaxf(m_i[qq], mx);
            const float corr = __expf(m_i[qq] - mnew);
            const float p1 = __expf(x1 - mnew);
            const float p2 = __expf(x2 - mnew);
            float ps = p1 + p2;
#pragma unroll
            for (int off = 16; off; off >>= 1)
                ps += __shfl_xor_sync(0xffffffffu, ps, off);
            l_i[qq] = l_i[qq] * corr + ps;
            o_i[qq] *= corr;
            m_i[qq] = mnew;
            Ss[r][lane] = p1;
            Ss[r][lane + 32] = p2;
        }
        __syncwarp();   // make this warp's P writes visible to all its lanes

        // O += P @ V  (each warp reads only its own 8 rows of Ss)
#pragma unroll
        for (int j4 = 0; j4 < 64; j4 += 4) {
            const float v0 = Vs[j4 + 0][lane];
            const float v1 = Vs[j4 + 1][lane];
            const float v2 = Vs[j4 + 2][lane];
            const float v3 = Vs[j4 + 3][lane];
#pragma unroll
            for (int qq = 0; qq < 8; qq++) {
                const float4 p = *(const float4*)&Ss[(warp << 3) + qq][j4];
                o_i[qq] = fmaf(p.x, v0, fmaf(p.y, v1, fmaf(p.z, v2, fmaf(p.w, v3, o_i[qq]))));
            }
        }
    }

#pragma unroll
    for (int qq = 0; qq < 8; qq++) {
        const int r = q0 + (warp << 3) + qq;
        O[(((size_t)b * NN + r) << 8) + (h << 5) + lane] = o_i[qq] / l_i[qq];
    }
}

// ============================================================================
// LayerNorm over last dim (256): out = (y-mu)*rsqrt(var+eps)*g + b
// ============================================================================
__global__ void __launch_bounds__(256) ln_kernel(
    const float* __restrict__ y, const float* __restrict__ g,
    const float* __restrict__ b, float* __restrict__ out)
{
    __shared__ float red[8];
    const int row = blockIdx.x, d = threadIdx.x;
    const int lane = d & 31, warp = d >> 5;
    const float v = y[(size_t)row * DD + d];

    float s = v;
#pragma unroll
    for (int off = 16; off; off >>= 1) s += __shfl_xor_sync(0xffffffffu, s, off);
    if (lane == 0) red[warp] = s;
    __syncthreads();
    float tot = red[0] + red[1] + red[2] + red[3] + red[4] + red[5] + red[6] + red[7];
    const float mu = tot * (1.0f / 256.0f);
    const float dv = v - mu;
    __syncthreads();

    float s2 = dv * dv;
#pragma unroll
    for (int off = 16; off; off >>= 1) s2 += __shfl_xor_sync(0xffffffffu, s2, off);
    if (lane == 0) red[warp] = s2;
    __syncthreads();
    float tot2 = red[0] + red[1] + red[2] + red[3] + red[4] + red[5] + red[6] + red[7];
    const float var = tot2 * (1.0f / 256.0f);

    out[(size_t)row * DD + d] = dv * rsqrtf(var + 1e-6f) * g[d] + b[d];
}

// ============================================================================
// host
// ============================================================================
static float* sym_addr(const void* sym) {
    void* p = nullptr;
    cudaGetSymbolAddress(&p, sym);
    return (float*)p;
}

extern "C" void kernel_launch(void* const* d_in, const int* in_sizes, int n_in,
                              void* d_out, int out_size)
{
    (void)n_in; (void)out_size;
    const float *x, *svd, *Wsvd, *bsvd, *ide, *ode, *spe;
    const float *Wq, *bq, *Wk, *bk, *Wv, *bv, *Wa, *ba, *g1, *lb1;
    const float *W1, *b1, *W2, *b2, *g2, *lb2;
    const int *ind, *outd, *spp;

    auto F = [&](int i) { return (const float*)d_in[i]; };
    auto I = [&](int i) { return (const int*)d_in[i]; };

    if (in_sizes[1] == 1024) {
        // setup_inputs() dict order
        x = F(0);  ind = I(1); outd = I(2); spp = I(3);
        svd = F(4); ide = F(5); ode = F(6); spe = F(7);
        Wsvd = F(8); bsvd = F(9);
        Wq = F(10); Wk = F(11); Wv = F(12); Wa = F(13); W1 = F(14); W2 = F(15);
        bq = F(16); bk = F(17); bv = F(18); ba = F(19); b1 = F(20); b2 = F(21);
        lb1 = F(22); lb2 = F(23); g1 = F(24); g2 = F(25);
    } else {
        // reference() signature order
        x = F(0); svd = F(1); Wsvd = F(2); bsvd = F(3);
        ide = F(4); ode = F(5); spe = F(6);
        Wq = F(7); bq = F(8); Wk = F(9); bk = F(10); Wv = F(11); bv = F(12);
        Wa = F(13); ba = F(14); g1 = F(15); lb1 = F(16);
        W1 = F(17); b1 = F(18); W2 = F(19); b2 = F(20); g2 = F(21); lb2 = F(22);
        ind = I(23); outd = I(24); spp = I(25);
    }

    float* h = sym_addr(g_h);
    float* q = sym_addr(g_q);
    float* k = sym_addr(g_k);
    float* v = sym_addr(g_v);
    float* o = sym_addr(g_o);
    float* y = sym_addr(g_y);
    float* f = sym_addr(g_f);
    float* out = (float*)d_out;

    const dim3 ggrid(DD / 64, MTOT / 64);   // (4, 64)
    const dim3 agrid(NN / 64, BB * HH);     // (16, 32)

    embed_kernel<<<MTOT, 256>>>(x, ind, outd, svd, Wsvd, bsvd, ide, ode, h);

    for (int l = 0; l < LL; l++) {
        const size_t wo = (size_t)l * DD * DD;
        const size_t bo = (size_t)l * DD;

        gemm_kernel<0><<<ggrid, 256>>>(h, Wq + wo, bq + bo, nullptr, q);
        gemm_kernel<0><<<ggrid, 256>>>(h, Wk + wo, bk + bo, nullptr, k);
        gemm_kernel<0><<<ggrid, 256>>>(h, Wv + wo, bv + bo, nullptr, v);

        attn_kernel<<<agrid, 256>>>(q, k, v, spp, spe, o);

        gemm_kernel<2><<<ggrid, 256>>>(o, Wa + wo, ba + bo, h, y);
        ln_kernel<<<MTOT, 256>>>(y, g1 + bo, lb1 + bo, h);

        gemm_kernel<1><<<ggrid, 256>>>(h, W1 + wo, b1 + bo, nullptr, f);
        gemm_kernel<2><<<ggrid, 256>>>(f, W2 + wo, b2 + bo, h, y);

        float* dst = (l == LL - 1) ? out : h;
        ln_kernel<<<MTOT, 256>>>(y, g2 + bo, lb2 + bo, dst);
    }
}

// round 4
// speedup vs baseline: 1.1220x; 1.1220x over previous
#include <cuda_runtime.h>
#include <cstdint>

#define BB 4
#define NN 1024
#define HH 8
#define DD 256
#define LL 4
#define MTOT (BB * NN)  // 4096

typedef unsigned long long ull;

// ---------------- packed fp32x2 helpers (sm_103a FFMA2) ----------------
__device__ __forceinline__ ull f2fma(ull a, ull b, ull c) {
    ull d; asm("fma.rn.f32x2 %0, %1, %2, %3;" : "=l"(d) : "l"(a), "l"(b), "l"(c)); return d;
}
__device__ __forceinline__ ull fdup(float x) {
    ull d; unsigned r = __float_as_uint(x);
    asm("mov.b64 %0, {%1, %1};" : "=l"(d) : "r"(r)); return d;
}
__device__ __forceinline__ ull fpack(float lo, float hi) {
    ull d; unsigned a = __float_as_uint(lo), b = __float_as_uint(hi);
    asm("mov.b64 %0, {%1, %2};" : "=l"(d) : "r"(a), "r"(b)); return d;
}
__device__ __forceinline__ float2 f2unp(ull v) {
    unsigned lo, hi; asm("mov.b64 {%0, %1}, %2;" : "=r"(lo), "=r"(hi) : "l"(v));
    return make_float2(__uint_as_float(lo), __uint_as_float(hi));
}

// ---------------- scratch buffers ----------------
__device__ float g_h[MTOT * DD];
__device__ float g_q[MTOT * DD];
__device__ float g_k[MTOT * DD];
__device__ float g_v[MTOT * DD];
__device__ float g_o[MTOT * DD];
__device__ float g_y[MTOT * DD];
__device__ float g_f[MTOT * DD];
__device__ float g_opart[2 * MTOT * DD];
__device__ float g_lpart[2 * MTOT * HH];

// ============================================================================
// embed
// ============================================================================
__global__ void __launch_bounds__(256) embed_kernel(
    const float* __restrict__ x, const int* __restrict__ ind,
    const int* __restrict__ outd, const float* __restrict__ svd,
    const float* __restrict__ Wsvd, const float* __restrict__ bsvd,
    const float* __restrict__ ide, const float* __restrict__ ode,
    float* __restrict__ h)
{
    int bn = blockIdx.x;
    int n  = bn & (NN - 1);
    int d  = threadIdx.x;
    __shared__ float pos[32];
    if (d < 32) {
        float v = svd[n * 32 + d];
        pos[d] = (d < 16) ? v : -v;
    }
    __syncthreads();
    int di = ind[n], do2 = outd[n];
    float acc = x[(size_t)bn * DD + d]
              + ide[(size_t)di * DD + d]
              + ode[(size_t)do2 * DD + d]
              + bsvd[d];
#pragma unroll
    for (int k = 0; k < 32; k++)
        acc = fmaf(pos[k], Wsvd[k * DD + d], acc);
    h[(size_t)bn * DD + d] = acc;
}

// ============================================================================
// GEMM core: 64x64 tile, K-chunks of 32, register-prefetched loads,
// fp32x2 packed FMA micro-kernel (4 rows x 2 pairs).
// EPI: 0 = bias, 1 = bias+relu, 2 = bias+residual
// ============================================================================
template <int EPI>
__device__ __forceinline__ void gemm_core(
    const float* __restrict__ X, const float* __restrict__ W,
    const float* __restrict__ bias, const float* __restrict__ res,
    float* __restrict__ Y, const int m0, const int n0)
{
    __shared__ __align__(16) float As[32][68];   // [k][m]
    __shared__ __align__(16) float Bs[32][64];   // [k][n]
    const int tid = threadIdx.x;
    const int tx = tid & 15, ty = tid >> 4;
    const int lr = tid >> 2;             // 0..63 X row
    const int lc = (tid & 3) << 2;       // X col base within chunk (0,4,8,12)
    const int wr = tid >> 4;             // 0..15 W row within chunk
    const int wc = (tid & 15) << 2;      // 0..60 W col

    // prologue: chunk 0
    {
        const float* Xp = &X[(size_t)(m0 + lr) * DD + lc];
        const float4 x0 = *(const float4*)Xp;
        const float4 x1 = *(const float4*)(Xp + 16);
        const float* Wp = &W[(size_t)wr * DD + n0 + wc];
        const float4 w0 = *(const float4*)Wp;
        const float4 w1 = *(const float4*)(Wp + 16 * DD);
        As[lc + 0][lr] = x0.x; As[lc + 1][lr] = x0.y;
        As[lc + 2][lr] = x0.z; As[lc + 3][lr] = x0.w;
        As[lc + 16][lr] = x1.x; As[lc + 17][lr] = x1.y;
        As[lc + 18][lr] = x1.z; As[lc + 19][lr] = x1.w;
        *(float4*)&Bs[wr][wc] = w0;
        *(float4*)&Bs[wr + 16][wc] = w1;
    }
    __syncthreads();

    ull acc2[4][2] = {};
#pragma unroll 1
    for (int c = 0; c < 8; c++) {
        float4 x0, x1, w0, w1;
        if (c < 7) {
            const float* Xp = &X[(size_t)(m0 + lr) * DD + (c + 1) * 32 + lc];
            x0 = *(const float4*)Xp;
            x1 = *(const float4*)(Xp + 16);
            const float* Wp = &W[(size_t)((c + 1) * 32 + wr) * DD + n0 + wc];
            w0 = *(const float4*)Wp;
            w1 = *(const float4*)(Wp + 16 * DD);
        }
#pragma unroll
        for (int kk = 0; kk < 32; kk++) {
            const float4 a4 = *(const float4*)&As[kk][ty << 2];
            const ulonglong2 b2 = *(const ulonglong2*)&Bs[kk][tx << 2];
            const ull ad0 = fdup(a4.x), ad1 = fdup(a4.y);
            const ull ad2 = fdup(a4.z), ad3 = fdup(a4.w);
            acc2[0][0] = f2fma(ad0, b2.x, acc2[0][0]);
            acc2[0][1] = f2fma(ad0, b2.y, acc2[0][1]);
            acc2[1][0] = f2fma(ad1, b2.x, acc2[1][0]);
            acc2[1][1] = f2fma(ad1, b2.y, acc2[1][1]);
            acc2[2][0] = f2fma(ad2, b2.x, acc2[2][0]);
            acc2[2][1] = f2fma(ad2, b2.y, acc2[2][1]);
            acc2[3][0] = f2fma(ad3, b2.x, acc2[3][0]);
            acc2[3][1] = f2fma(ad3, b2.y, acc2[3][1]);
        }
        __syncthreads();
        if (c < 7) {
            As[lc + 0][lr] = x0.x; As[lc + 1][lr] = x0.y;
            As[lc + 2][lr] = x0.z; As[lc + 3][lr] = x0.w;
            As[lc + 16][lr] = x1.x; As[lc + 17][lr] = x1.y;
            As[lc + 18][lr] = x1.z; As[lc + 19][lr] = x1.w;
            *(float4*)&Bs[wr][wc] = w0;
            *(float4*)&Bs[wr + 16][wc] = w1;
            __syncthreads();
        }
    }

    const float4 bb = *(const float4*)&bias[n0 + (tx << 2)];
#pragma unroll
    for (int i = 0; i < 4; i++) {
        const int row = m0 + (ty << 2) + i;
        const float2 a01 = f2unp(acc2[i][0]);
        const float2 a23 = f2unp(acc2[i][1]);
        float4 o;
        o.x = a01.x + bb.x; o.y = a01.y + bb.y;
        o.z = a23.x + bb.z; o.w = a23.y + bb.w;
        if (EPI == 2) {
            const float4 r4 = *(const float4*)&res[(size_t)row * DD + n0 + (tx << 2)];
            o.x += r4.x; o.y += r4.y; o.z += r4.z; o.w += r4.w;
        }
        if (EPI == 1) {
            o.x = fmaxf(o.x, 0.f); o.y = fmaxf(o.y, 0.f);
            o.z = fmaxf(o.z, 0.f); o.w = fmaxf(o.w, 0.f);
        }
        *(float4*)&Y[(size_t)row * DD + n0 + (tx << 2)] = o;
    }
}

template <int EPI>
__global__ void __launch_bounds__(256) gemm_kernel(
    const float* __restrict__ X, const float* __restrict__ W,
    const float* __restrict__ bias, const float* __restrict__ res,
    float* __restrict__ Y)
{
    gemm_core<EPI>(X, W, bias, res, Y, blockIdx.y << 6, blockIdx.x << 6);
}

// fused QKV: grid (12, 64); blockIdx.x>>2 selects Q/K/V, &3 -> n-tile
__global__ void __launch_bounds__(256) qkv_kernel(
    const float* __restrict__ h,
    const float* __restrict__ Wq, const float* __restrict__ Wk, const float* __restrict__ Wv,
    const float* __restrict__ bq, const float* __restrict__ bk, const float* __restrict__ bv,
    float* __restrict__ q, float* __restrict__ k, float* __restrict__ v)
{
    const int sel = blockIdx.x >> 2;
    const int n0 = (blockIdx.x & 3) << 6;
    const int m0 = blockIdx.y << 6;
    const float* W = (sel == 0) ? Wq : (sel == 1) ? Wk : Wv;
    const float* B = (sel == 0) ? bq : (sel == 1) ? bk : bv;
    float* Y       = (sel == 0) ? q  : (sel == 1) ? k  : v;
    gemm_core<0>(h, W, B, nullptr, Y, m0, n0);
}

// ============================================================================
// Flash attention, split-K=2, no-max softmax (scores provably tiny),
// fp32x2 for both QK^T and PV. Writes unnormalized o and row-sums l.
// grid (16 q-tiles, 2 splits, 32 bh), 256 threads.
// ============================================================================
struct KV4 { float4 k0, k1, v0, v1; };

__device__ __forceinline__ KV4 load_kv(const float* __restrict__ K,
                                       const float* __restrict__ V,
                                       int b, int h, int kstart, int tid)
{
    KV4 r;
    const int i0 = tid, i1 = tid + 256;
    const int r0 = i0 >> 3, c0 = (i0 & 7) << 2;
    const int r1 = i1 >> 3, c1 = (i1 & 7) << 2;
    const size_t base0 = (((size_t)b * NN + kstart + r0) << 8) + (h << 5) + c0;
    const size_t base1 = (((size_t)b * NN + kstart + r1) << 8) + (h << 5) + c1;
    r.k0 = *(const float4*)&K[base0]; r.k1 = *(const float4*)&K[base1];
    r.v0 = *(const float4*)&V[base0]; r.v1 = *(const float4*)&V[base1];
    return r;
}

__global__ void __launch_bounds__(256) attn_kernel(
    const float* __restrict__ Q, const float* __restrict__ K,
    const float* __restrict__ V, const int* __restrict__ spp,
    const float* __restrict__ spe,
    float* __restrict__ o_part, float* __restrict__ l_part)
{
    __shared__ __align__(16) float Qst[32][68];   // [dk][q]
    __shared__ __align__(16) float Kst[32][68];   // [dk][k]
    __shared__ __align__(16) float Vs[64][36];    // [k][dk]
    __shared__ __align__(16) float Ss[64][64];    // [q][k] -> holds P=exp(S)

    const int tid  = threadIdx.x;
    const int lane = tid & 31, warp = tid >> 5;
    const int tx = tid & 15, ty = tid >> 4;
    const int q0 = blockIdx.x << 6;
    const int split = blockIdx.y;
    const int bh = blockIdx.z;
    const int b  = bh >> 3, h = bh & 7;
    const int k_base = split << 9;                // 512 keys per split
    const float scale = 0.17677669529663687f;     // 1/sqrt(32)
    const float* __restrict__ speh = spe + h;

    // Q tile (transposed to [dk][q])
#pragma unroll
    for (int i = tid; i < 512; i += 256) {
        const int r = i >> 3, c = (i & 7) << 2;
        const float4 v4 = *(const float4*)&Q[(((size_t)b * NN + q0 + r) << 8) + (h << 5) + c];
        Qst[c + 0][r] = v4.x; Qst[c + 1][r] = v4.y;
        Qst[c + 2][r] = v4.z; Qst[c + 3][r] = v4.w;
    }

    // prologue: K/V tile 0
    {
        KV4 d = load_kv(K, V, b, h, k_base, tid);
        const int i0 = tid, i1 = tid + 256;
        const int r0 = i0 >> 3, c0 = (i0 & 7) << 2;
        const int r1 = i1 >> 3, c1 = (i1 & 7) << 2;
        Kst[c0 + 0][r0] = d.k0.x; Kst[c0 + 1][r0] = d.k0.y;
        Kst[c0 + 2][r0] = d.k0.z; Kst[c0 + 3][r0] = d.k0.w;
        Kst[c1 + 0][r1] = d.k1.x; Kst[c1 + 1][r1] = d.k1.y;
        Kst[c1 + 2][r1] = d.k1.z; Kst[c1 + 3][r1] = d.k1.w;
        *(float4*)&Vs[r0][c0] = d.v0;
        *(float4*)&Vs[r1][c1] = d.v1;
    }
    __syncthreads();

    ull o2[8];
    float lp[4] = {0.f, 0.f, 0.f, 0.f};
#pragma unroll
    for (int qq = 0; qq < 8; qq++) o2[qq] = 0ull;

#pragma unroll 1
    for (int t = 0; t < 8; t++) {
        const int k0 = k_base + (t << 6);
        KV4 nxt;
        if (t < 7) nxt = load_kv(K, V, b, h, k0 + 64, tid);

        // ---- S = Q K^T (fp32x2) ----
        ull acc2[4][2] = {};
#pragma unroll
        for (int kk = 0; kk < 32; kk++) {
            const float4 a4 = *(const float4*)&Qst[kk][ty << 2];
            const ulonglong2 b2 = *(const ulonglong2*)&Kst[kk][tx << 2];
            const ull ad0 = fdup(a4.x), ad1 = fdup(a4.y);
            const ull ad2 = fdup(a4.z), ad3 = fdup(a4.w);
            acc2[0][0] = f2fma(ad0, b2.x, acc2[0][0]);
            acc2[0][1] = f2fma(ad0, b2.y, acc2[0][1]);
            acc2[1][0] = f2fma(ad1, b2.x, acc2[1][0]);
            acc2[1][1] = f2fma(ad1, b2.y, acc2[1][1]);
            acc2[2][0] = f2fma(ad2, b2.x, acc2[2][0]);
            acc2[2][1] = f2fma(ad2, b2.y, acc2[2][1]);
            acc2[3][0] = f2fma(ad3, b2.x, acc2[3][0]);
            acc2[3][1] = f2fma(ad3, b2.y, acc2[3][1]);
        }

        // ---- epilogue: scale + bias gather + exp, store P, l partials ----
#pragma unroll
        for (int i = 0; i < 4; i++) {
            const int qg = q0 + (ty << 2) + i;
            const int4 sp4 = *(const int4*)&spp[(size_t)qg * NN + k0 + (tx << 2)];
            const float2 a01 = f2unp(acc2[i][0]);
            const float2 a23 = f2unp(acc2[i][1]);
            float4 p;
            p.x = __expf(fmaf(a01.x, scale, speh[sp4.x * HH]));
            p.y = __expf(fmaf(a01.y, scale, speh[sp4.y * HH]));
            p.z = __expf(fmaf(a23.x, scale, speh[sp4.z * HH]));
            p.w = __expf(fmaf(a23.y, scale, speh[sp4.w * HH]));
            *(float4*)&Ss[(ty << 2) + i][tx << 2] = p;
            lp[i] += (p.x + p.y) + (p.z + p.w);
        }
        __syncwarp();   // P rows for this warp are written by this warp only

        // ---- O += P V (fp32x2, pairs over keys) ----
#pragma unroll
        for (int j4 = 0; j4 < 64; j4 += 4) {
            const ull v01 = fpack(Vs[j4 + 0][lane], Vs[j4 + 1][lane]);
            const ull v23 = fpack(Vs[j4 + 2][lane], Vs[j4 + 3][lane]);
#pragma unroll
            for (int qq = 0; qq < 8; qq++) {
                const ulonglong2 pp = *(const ulonglong2*)&Ss[(warp << 3) + qq][j4];
                o2[qq] = f2fma(pp.x, v01, o2[qq]);
                o2[qq] = f2fma(pp.y, v23, o2[qq]);
            }
        }
        __syncthreads();   // all reads of Kst/Vs/Ss done
        if (t < 7) {
            const int i0 = tid, i1 = tid + 256;
            const int r0 = i0 >> 3, c0 = (i0 & 7) << 2;
            const int r1 = i1 >> 3, c1 = (i1 & 7) << 2;
            Kst[c0 + 0][r0] = nxt.k0.x; Kst[c0 + 1][r0] = nxt.k0.y;
            Kst[c0 + 2][r0] = nxt.k0.z; Kst[c0 + 3][r0] = nxt.k0.w;
            Kst[c1 + 0][r1] = nxt.k1.x; Kst[c1 + 1][r1] = nxt.k1.y;
            Kst[c1 + 2][r1] = nxt.k1.z; Kst[c1 + 3][r1] = nxt.k1.w;
            *(float4*)&Vs[r0][c0] = nxt.v0;
            *(float4*)&Vs[r1][c1] = nxt.v1;
            __syncthreads();
        }
    }

    // reduce row sums within each 16-lane half (tx covers all 64 cols)
#pragma unroll
    for (int i = 0; i < 4; i++) {
        lp[i] += __shfl_xor_sync(0xffffffffu, lp[i], 8);
        lp[i] += __shfl_xor_sync(0xffffffffu, lp[i], 4);
        lp[i] += __shfl_xor_sync(0xffffffffu, lp[i], 2);
        lp[i] += __shfl_xor_sync(0xffffffffu, lp[i], 1);
    }

    const size_t sb = (size_t)split * MTOT + (size_t)b * NN;
#pragma unroll
    for (int qq = 0; qq < 8; qq++) {
        const int row = q0 + (warp << 3) + qq;
        const float lsum = __shfl_sync(0xffffffffu, lp[qq & 3], (qq >> 2) << 4);
        const float2 oo = f2unp(o2[qq]);
        o_part[((sb + row) << 8) + (h << 5) + lane] = oo.x + oo.y;
        if (lane == 0) l_part[(sb + row) * HH + h] = lsum;
    }
}

// merge the two split-K partials: O = (o0+o1)/(l0+l1)
__global__ void __launch_bounds__(256) merge_kernel(
    const float* __restrict__ o_part, const float* __restrict__ l_part,
    float* __restrict__ O)
{
    const int idx = blockIdx.x * 256 + threadIdx.x;   // over MTOT*DD
    const int bn = idx >> 8;
    const int h = (idx >> 5) & 7;
    const float o0 = o_part[idx];
    const float o1 = o_part[idx + MTOT * DD];
    const float l0 = l_part[bn * HH + h];
    const float l1 = l_part[bn * HH + h + MTOT * HH];
    O[idx] = (o0 + o1) / (l0 + l1);
}

// ============================================================================
// LayerNorm over last dim (256)
// ============================================================================
__global__ void __launch_bounds__(256) ln_kernel(
    const float* __restrict__ y, const float* __restrict__ g,
    const float* __restrict__ b, float* __restrict__ out)
{
    __shared__ float red[8];
    const int row = blockIdx.x, d = threadIdx.x;
    const int lane = d & 31, warp = d >> 5;
    const float v = y[(size_t)row * DD + d];

    float s = v;
#pragma unroll
    for (int off = 16; off; off >>= 1) s += __shfl_xor_sync(0xffffffffu, s, off);
    if (lane == 0) red[warp] = s;
    __syncthreads();
    float tot = red[0] + red[1] + red[2] + red[3] + red[4] + red[5] + red[6] + red[7];
    const float mu = tot * (1.0f / 256.0f);
    const float dv = v - mu;
    __syncthreads();

    float s2 = dv * dv;
#pragma unroll
    for (int off = 16; off; off >>= 1) s2 += __shfl_xor_sync(0xffffffffu, s2, off);
    if (lane == 0) red[warp] = s2;
    __syncthreads();
    float tot2 = red[0] + red[1] + red[2] + red[3] + red[4] + red[5] + red[6] + red[7];
    const float var = tot2 * (1.0f / 256.0f);

    out[(size_t)row * DD + d] = dv * rsqrtf(var + 1e-6f) * g[d] + b[d];
}

// ============================================================================
// host
// ============================================================================
static float* sym_addr(const void* sym) {
    void* p = nullptr;
    cudaGetSymbolAddress(&p, sym);
    return (float*)p;
}

extern "C" void kernel_launch(void* const* d_in, const int* in_sizes, int n_in,
                              void* d_out, int out_size)
{
    (void)n_in; (void)out_size;
    const float *x, *svd, *Wsvd, *bsvd, *ide, *ode, *spe;
    const float *Wq, *bq, *Wk, *bk, *Wv, *bv, *Wa, *ba, *g1, *lb1;
    const float *W1, *b1, *W2, *b2, *g2, *lb2;
    const int *ind, *outd, *spp;

    auto F = [&](int i) { return (const float*)d_in[i]; };
    auto I = [&](int i) { return (const int*)d_in[i]; };

    if (in_sizes[1] == 1024) {
        x = F(0);  ind = I(1); outd = I(2); spp = I(3);
        svd = F(4); ide = F(5); ode = F(6); spe = F(7);
        Wsvd = F(8); bsvd = F(9);
        Wq = F(10); Wk = F(11); Wv = F(12); Wa = F(13); W1 = F(14); W2 = F(15);
        bq = F(16); bk = F(17); bv = F(18); ba = F(19); b1 = F(20); b2 = F(21);
        lb1 = F(22); lb2 = F(23); g1 = F(24); g2 = F(25);
    } else {
        x = F(0); svd = F(1); Wsvd = F(2); bsvd = F(3);
        ide = F(4); ode = F(5); spe = F(6);
        Wq = F(7); bq = F(8); Wk = F(9); bk = F(10); Wv = F(11); bv = F(12);
        Wa = F(13); ba = F(14); g1 = F(15); lb1 = F(16);
        W1 = F(17); b1 = F(18); W2 = F(19); b2 = F(20); g2 = F(21); lb2 = F(22);
        ind = I(23); outd = I(24); spp = I(25);
    }

    float* h = sym_addr(g_h);
    float* q = sym_addr(g_q);
    float* k = sym_addr(g_k);
    float* v = sym_addr(g_v);
    float* o = sym_addr(g_o);
    float* y = sym_addr(g_y);
    float* f = sym_addr(g_f);
    float* opart = sym_addr(g_opart);
    float* lpart = sym_addr(g_lpart);
    float* out = (float*)d_out;

    const dim3 ggrid(DD / 64, MTOT / 64);     // (4, 64)
    const dim3 qgrid(12, MTOT / 64);          // fused QKV
    const dim3 agrid(NN / 64, 2, BB * HH);    // (16, 2, 32)

    embed_kernel<<<MTOT, 256>>>(x, ind, outd, svd, Wsvd, bsvd, ide, ode, h);

    for (int l = 0; l < LL; l++) {
        const size_t wo = (size_t)l * DD * DD;
        const size_t bo = (size_t)l * DD;

        qkv_kernel<<<qgrid, 256>>>(h, Wq + wo, Wk + wo, Wv + wo,
                                   bq + bo, bk + bo, bv + bo, q, k, v);

        attn_kernel<<<agrid, 256>>>(q, k, v, spp, spe, opart, lpart);
        merge_kernel<<<MTOT, 256>>>(opart, lpart, o);

        gemm_kernel<2><<<ggrid, 256>>>(o, Wa + wo, ba + bo, h, y);
        ln_kernel<<<MTOT, 256>>>(y, g1 + bo, lb1 + bo, h);

        gemm_kernel<1><<<ggrid, 256>>>(h, W1 + wo, b1 + bo, nullptr, f);
        gemm_kernel<2><<<ggrid, 256>>>(f, W2 + wo, b2 + bo, h, y);

        float* dst = (l == LL - 1) ? out : h;
        ln_kernel<<<MTOT, 256>>>(y, g2 + bo, lb2 + bo, dst);
    }
}

// round 6
// speedup vs baseline: 1.3308x; 1.1861x over previous
#include <cuda_runtime.h>
#include <cstdint>

#define BB 4
#define NN 1024
#define HH 8
#define DD 256
#define LL 4
#define MTOT (BB * NN)  // 4096

typedef unsigned long long ull;

// ---------------- packed fp32x2 helpers (sm_103a FFMA2) ----------------
__device__ __forceinline__ ull f2fma(ull a, ull b, ull c) {
    ull d; asm("fma.rn.f32x2 %0, %1, %2, %3;" : "=l"(d) : "l"(a), "l"(b), "l"(c)); return d;
}
__device__ __forceinline__ ull fdup(float x) {
    ull d; unsigned r = __float_as_uint(x);
    asm("mov.b64 %0, {%1, %1};" : "=l"(d) : "r"(r)); return d;
}
__device__ __forceinline__ ull fpack(float lo, float hi) {
    ull d; unsigned a = __float_as_uint(lo), b = __float_as_uint(hi);
    asm("mov.b64 %0, {%1, %2};" : "=l"(d) : "r"(a), "r"(b)); return d;
}
__device__ __forceinline__ float2 f2unp(ull v) {
    unsigned lo, hi; asm("mov.b64 {%0, %1}, %2;" : "=r"(lo), "=r"(hi) : "l"(v));
    return make_float2(__uint_as_float(lo), __uint_as_float(hi));
}

// ---------------- scratch buffers ----------------
__device__ float g_h[MTOT * DD];
__device__ float g_q[MTOT * DD];
__device__ float g_k[MTOT * DD];
__device__ float g_v[MTOT * DD];
__device__ float g_o[MTOT * DD];
__device__ float g_y[MTOT * DD];
__device__ float g_f[MTOT * DD];
__device__ float g_bias[HH * NN * NN];   // 32MB precomputed attention bias [h][q][k]

// ============================================================================
// bias precompute: bias[h][q][k] = spe[spp[q][k]*H + h]
// one thread per (q,k); spe row is a 32B contiguous gather (L1-hot table);
// 8 plane-writes, each coalesced across the warp.
// ============================================================================
__global__ void __launch_bounds__(256) bias_kernel(
    const int* __restrict__ spp, const float* __restrict__ spe,
    float* __restrict__ bias)
{
    const int idx = blockIdx.x * 256 + threadIdx.x;   // over N*N
    const int sp = spp[idx];
    const float4 e0 = *(const float4*)&spe[sp * 8];
    const float4 e1 = *(const float4*)&spe[sp * 8 + 4];
    bias[0 * NN * NN + idx] = e0.x;
    bias[1 * NN * NN + idx] = e0.y;
    bias[2 * NN * NN + idx] = e0.z;
    bias[3 * NN * NN + idx] = e0.w;
    bias[4 * NN * NN + idx] = e1.x;
    bias[5 * NN * NN + idx] = e1.y;
    bias[6 * NN * NN + idx] = e1.z;
    bias[7 * NN * NN + idx] = e1.w;
}

// ============================================================================
// embed
// ============================================================================
__global__ void __launch_bounds__(256) embed_kernel(
    const float* __restrict__ x, const int* __restrict__ ind,
    const int* __restrict__ outd, const float* __restrict__ svd,
    const float* __restrict__ Wsvd, const float* __restrict__ bsvd,
    const float* __restrict__ ide, const float* __restrict__ ode,
    float* __restrict__ h)
{
    int bn = blockIdx.x;
    int n  = bn & (NN - 1);
    int d  = threadIdx.x;
    __shared__ float pos[32];
    if (d < 32) {
        float v = svd[n * 32 + d];
        pos[d] = (d < 16) ? v : -v;
    }
    __syncthreads();
    int di = ind[n], do2 = outd[n];
    float acc = x[(size_t)bn * DD + d]
              + ide[(size_t)di * DD + d]
              + ode[(size_t)do2 * DD + d]
              + bsvd[d];
#pragma unroll
    for (int k = 0; k < 32; k++)
        acc = fmaf(pos[k], Wsvd[k * DD + d], acc);
    h[(size_t)bn * DD + d] = acc;
}

// ============================================================================
// GEMM core: 128x64 tile, K-chunks of 32, register-prefetched global loads,
// fp32x2 packed FMA micro-kernel (8 rows x 2 pairs per thread).
// EPI: 0 = bias, 1 = bias+relu, 2 = bias+residual
// ============================================================================
template <int EPI>
__device__ __forceinline__ void gemm_core(
    const float* __restrict__ X, const float* __restrict__ W,
    const float* __restrict__ bias, const float* __restrict__ res,
    float* __restrict__ Y, const int m0, const int n0)
{
    __shared__ __align__(16) float As[32][132];  // [k][m], 128+4 pad
    __shared__ __align__(16) float Bs[32][64];   // [k][n]
    const int tid = threadIdx.x;
    const int tx = tid & 15, ty = tid >> 4;      // 16 col-groups x 16 row-groups
    const int lr = tid >> 1;                     // 0..127  X row
    const int lc = (tid & 1) << 4;               // 0 or 16 (chunk-col base)
    const int wr = tid >> 3;                     // 0..31   W row within chunk
    const int wc = (tid & 7) << 3;               // 0..56   W col base

    float4 xr[4], wv[2];
    // prologue: load chunk 0
    {
        const float* Xp = &X[(size_t)(m0 + lr) * DD + lc];
#pragma unroll
        for (int j = 0; j < 4; j++) xr[j] = *(const float4*)(Xp + 4 * j);
        const float* Wp = &W[(size_t)wr * DD + n0 + wc];
        wv[0] = *(const float4*)Wp;
        wv[1] = *(const float4*)(Wp + 4);
    }
#pragma unroll
    for (int j = 0; j < 4; j++) {
        As[lc + 4 * j + 0][lr] = xr[j].x;
        As[lc + 4 * j + 1][lr] = xr[j].y;
        As[lc + 4 * j + 2][lr] = xr[j].z;
        As[lc + 4 * j + 3][lr] = xr[j].w;
    }
    *(float4*)&Bs[wr][wc] = wv[0];
    *(float4*)&Bs[wr][wc + 4] = wv[1];
    __syncthreads();

    ull acc2[8][2] = {};
#pragma unroll 1
    for (int c = 0; c < 8; c++) {
        if (c < 7) {
            const float* Xp = &X[(size_t)(m0 + lr) * DD + (c + 1) * 32 + lc];
#pragma unroll
            for (int j = 0; j < 4; j++) xr[j] = *(const float4*)(Xp + 4 * j);
            const float* Wp = &W[(size_t)((c + 1) * 32 + wr) * DD + n0 + wc];
            wv[0] = *(const float4*)Wp;
            wv[1] = *(const float4*)(Wp + 4);
        }
#pragma unroll
        for (int kk = 0; kk < 32; kk++) {
            const float4 a0 = *(const float4*)&As[kk][ty << 3];
            const float4 a1 = *(const float4*)&As[kk][(ty << 3) + 4];
            const ulonglong2 b2 = *(const ulonglong2*)&Bs[kk][tx << 2];
            const float av[8] = {a0.x, a0.y, a0.z, a0.w, a1.x, a1.y, a1.z, a1.w};
#pragma unroll
            for (int i = 0; i < 8; i++) {
                const ull ad = fdup(av[i]);
                acc2[i][0] = f2fma(ad, b2.x, acc2[i][0]);
                acc2[i][1] = f2fma(ad, b2.y, acc2[i][1]);
            }
        }
        __syncthreads();
        if (c < 7) {
#pragma unroll
            for (int j = 0; j < 4; j++) {
                As[lc + 4 * j + 0][lr] = xr[j].x;
                As[lc + 4 * j + 1][lr] = xr[j].y;
                As[lc + 4 * j + 2][lr] = xr[j].z;
                As[lc + 4 * j + 3][lr] = xr[j].w;
            }
            *(float4*)&Bs[wr][wc] = wv[0];
            *(float4*)&Bs[wr][wc + 4] = wv[1];
            __syncthreads();
        }
    }

    const float4 bb = *(const float4*)&bias[n0 + (tx << 2)];
#pragma unroll
    for (int i = 0; i < 8; i++) {
        const int row = m0 + (ty << 3) + i;
        const float2 a01 = f2unp(acc2[i][0]);
        const float2 a23 = f2unp(acc2[i][1]);
        float4 o;
        o.x = a01.x + bb.x; o.y = a01.y + bb.y;
        o.z = a23.x + bb.z; o.w = a23.y + bb.w;
        if (EPI == 2) {
            const float4 r4 = *(const float4*)&res[(size_t)row * DD + n0 + (tx << 2)];
            o.x += r4.x; o.y += r4.y; o.z += r4.z; o.w += r4.w;
        }
        if (EPI == 1) {
            o.x = fmaxf(o.x, 0.f); o.y = fmaxf(o.y, 0.f);
            o.z = fmaxf(o.z, 0.f); o.w = fmaxf(o.w, 0.f);
        }
        *(float4*)&Y[(size_t)row * DD + n0 + (tx << 2)] = o;
    }
}

template <int EPI>
__global__ void __launch_bounds__(256) gemm_kernel(
    const float* __restrict__ X, const float* __restrict__ W,
    const float* __restrict__ bias, const float* __restrict__ res,
    float* __restrict__ Y)
{
    gemm_core<EPI>(X, W, bias, res, Y, blockIdx.y << 7, blockIdx.x << 6);
}

// fused QKV: grid (12, 32); blockIdx.x>>2 selects Q/K/V, &3 -> n-tile
__global__ void __launch_bounds__(256) qkv_kernel(
    const float* __restrict__ h,
    const float* __restrict__ Wq, const float* __restrict__ Wk, const float* __restrict__ Wv,
    const float* __restrict__ bq, const float* __restrict__ bk, const float* __restrict__ bv,
    float* __restrict__ q, float* __restrict__ k, float* __restrict__ v)
{
    const int sel = blockIdx.x >> 2;
    const int n0 = (blockIdx.x & 3) << 6;
    const int m0 = blockIdx.y << 7;
    const float* W = (sel == 0) ? Wq : (sel == 1) ? Wk : Wv;
    const float* B = (sel == 0) ? bq : (sel == 1) ? bk : bv;
    float* Y       = (sel == 0) ? q  : (sel == 1) ? k  : v;
    gemm_core<0>(h, W, B, nullptr, Y, m0, n0);
}

// ============================================================================
// Flash attention, no-max softmax, precomputed bias table (coalesced loads),
// fp32x2 for QK^T and PV. grid (16 q-tiles, 32 bh), 256 threads, full K sweep.
// ============================================================================
struct KV4 { float4 k0, k1, v0, v1; };

__device__ __forceinline__ KV4 load_kv(const float* __restrict__ K,
                                       const float* __restrict__ V,
                                       int b, int h, int kstart, int tid)
{
    KV4 r;
    const int i0 = tid, i1 = tid + 256;
    const int r0 = i0 >> 3, c0 = (i0 & 7) << 2;
    const int r1 = i1 >> 3, c1 = (i1 & 7) << 2;
    const size_t base0 = (((size_t)b * NN + kstart + r0) << 8) + (h << 5) + c0;
    const size_t base1 = (((size_t)b * NN + kstart + r1) << 8) + (h << 5) + c1;
    r.k0 = *(const float4*)&K[base0]; r.k1 = *(const float4*)&K[base1];
    r.v0 = *(const float4*)&V[base0]; r.v1 = *(const float4*)&V[base1];
    return r;
}

__global__ void __launch_bounds__(256) attn_kernel(
    const float* __restrict__ Q, const float* __restrict__ K,
    const float* __restrict__ V, const float* __restrict__ bias,
    float* __restrict__ O)
{
    __shared__ __align__(16) float Qst[32][68];   // [dk][q]
    __shared__ __align__(16) float Kst[32][68];   // [dk][k]
    __shared__ __align__(16) float Vs[64][36];    // [k][dk]
    __shared__ __align__(16) float Ss[64][64];    // [q][k] -> P = exp

    const int tid  = threadIdx.x;
    const int lane = tid & 31, warp = tid >> 5;
    const int tx = tid & 15, ty = tid >> 4;
    const int q0 = blockIdx.x << 6;
    const int bh = blockIdx.y;
    const int b  = bh >> 3, h = bh & 7;
    const float scale = 0.17677669529663687f;     // 1/sqrt(32)
    const float* __restrict__ bias_h = bias + ((size_t)h << 20);

    // Q tile (transposed to [dk][q])
#pragma unroll
    for (int i = tid; i < 512; i += 256) {
        const int r = i >> 3, c = (i & 7) << 2;
        const float4 v4 = *(const float4*)&Q[(((size_t)b * NN + q0 + r) << 8) + (h << 5) + c];
        Qst[c + 0][r] = v4.x; Qst[c + 1][r] = v4.y;
        Qst[c + 2][r] = v4.z; Qst[c + 3][r] = v4.w;
    }

    // prologue K/V tile 0
    {
        KV4 d = load_kv(K, V, b, h, 0, tid);
        const int i0 = tid, i1 = tid + 256;
        const int r0 = i0 >> 3, c0 = (i0 & 7) << 2;
        const int r1 = i1 >> 3, c1 = (i1 & 7) << 2;
        Kst[c0 + 0][r0] = d.k0.x; Kst[c0 + 1][r0] = d.k0.y;
        Kst[c0 + 2][r0] = d.k0.z; Kst[c0 + 3][r0] = d.k0.w;
        Kst[c1 + 0][r1] = d.k1.x; Kst[c1 + 1][r1] = d.k1.y;
        Kst[c1 + 2][r1] = d.k1.z; Kst[c1 + 3][r1] = d.k1.w;
        *(float4*)&Vs[r0][c0] = d.v0;
        *(float4*)&Vs[r1][c1] = d.v1;
    }
    __syncthreads();

    ull o2[8];
    float lp[4] = {0.f, 0.f, 0.f, 0.f};
#pragma unroll
    for (int qq = 0; qq < 8; qq++) o2[qq] = 0ull;

#pragma unroll 1
    for (int t = 0; t < 16; t++) {
        const int k0 = t << 6;
        KV4 nxt;
        if (t < 15) nxt = load_kv(K, V, b, h, k0 + 64, tid);

        // ---- S = Q K^T (fp32x2) ----
        ull acc2[4][2] = {};
#pragma unroll
        for (int kk = 0; kk < 32; kk++) {
            const float4 a4 = *(const float4*)&Qst[kk][ty << 2];
            const ulonglong2 b2 = *(const ulonglong2*)&Kst[kk][tx << 2];
            const ull ad0 = fdup(a4.x), ad1 = fdup(a4.y);
            const ull ad2 = fdup(a4.z), ad3 = fdup(a4.w);
            acc2[0][0] = f2fma(ad0, b2.x, acc2[0][0]);
            acc2[0][1] = f2fma(ad0, b2.y, acc2[0][1]);
            acc2[1][0] = f2fma(ad1, b2.x, acc2[1][0]);
            acc2[1][1] = f2fma(ad1, b2.y, acc2[1][1]);
            acc2[2][0] = f2fma(ad2, b2.x, acc2[2][0]);
            acc2[2][1] = f2fma(ad2, b2.y, acc2[2][1]);
            acc2[3][0] = f2fma(ad3, b2.x, acc2[3][0]);
            acc2[3][1] = f2fma(ad3, b2.y, acc2[3][1]);
        }

        // ---- epilogue: scale + coalesced bias + exp, store P, l partials ----
#pragma unroll
        for (int i = 0; i < 4; i++) {
            const int qg = q0 + (ty << 2) + i;
            const float4 bb4 = *(const float4*)&bias_h[((size_t)qg << 10) + k0 + (tx << 2)];
            const float2 a01 = f2unp(acc2[i][0]);
            const float2 a23 = f2unp(acc2[i][1]);
            float4 p;
            p.x = __expf(fmaf(a01.x, scale, bb4.x));
            p.y = __expf(fmaf(a01.y, scale, bb4.y));
            p.z = __expf(fmaf(a23.x, scale, bb4.z));
            p.w = __expf(fmaf(a23.y, scale, bb4.w));
            *(float4*)&Ss[(ty << 2) + i][tx << 2] = p;
            lp[i] += (p.x + p.y) + (p.z + p.w);
        }
        __syncwarp();   // P rows for this warp are written only by this warp

        // ---- O += P V (fp32x2, pairs over keys) ----
#pragma unroll
        for (int j4 = 0; j4 < 64; j4 += 4) {
            const ull v01 = fpack(Vs[j4 + 0][lane], Vs[j4 + 1][lane]);
            const ull v23 = fpack(Vs[j4 + 2][lane], Vs[j4 + 3][lane]);
#pragma unroll
            for (int qq = 0; qq < 8; qq++) {
                const ulonglong2 pp = *(const ulonglong2*)&Ss[(warp << 3) + qq][j4];
                o2[qq] = f2fma(pp.x, v01, o2[qq]);
                o2[qq] = f2fma(pp.y, v23, o2[qq]);
            }
        }
        __syncthreads();
        if (t < 15) {
            const int i0 = tid, i1 = tid + 256;
            const int r0 = i0 >> 3, c0 = (i0 & 7) << 2;
            const int r1 = i1 >> 3, c1 = (i1 & 7) << 2;
            Kst[c0 + 0][r0] = nxt.k0.x; Kst[c0 + 1][r0] = nxt.k0.y;
            Kst[c0 + 2][r0] = nxt.k0.z; Kst[c0 + 3][r0] = nxt.k0.w;
            Kst[c1 + 0][r1] = nxt.k1.x; Kst[c1 + 1][r1] = nxt.k1.y;
            Kst[c1 + 2][r1] = nxt.k1.z; Kst[c1 + 3][r1] = nxt.k1.w;
            *(float4*)&Vs[r0][c0] = nxt.v0;
            *(float4*)&Vs[r1][c1] = nxt.v1;
            __syncthreads();
        }
    }

    // reduce row sums across the 16 tx lanes in each half-warp
#pragma unroll
    for (int i = 0; i < 4; i++) {
        lp[i] += __shfl_xor_sync(0xffffffffu, lp[i], 8);
        lp[i] += __shfl_xor_sync(0xffffffffu, lp[i], 4);
        lp[i] += __shfl_xor_sync(0xffffffffu, lp[i], 2);
        lp[i] += __shfl_xor_sync(0xffffffffu, lp[i], 1);
    }

#pragma unroll
    for (int qq = 0; qq < 8; qq++) {
        const int row = q0 + (warp << 3) + qq;
        const float lsum = __shfl_sync(0xffffffffu, lp[qq & 3], (qq >> 2) << 4);
        const float2 oo = f2unp(o2[qq]);
        O[(((size_t)b * NN + row) << 8) + (h << 5) + lane] = (oo.x + oo.y) / lsum;
    }
}

// ============================================================================
// LayerNorm over last dim (256)
// ============================================================================
__global__ void __launch_bounds__(256) ln_kernel(
    const float* __restrict__ y, const float* __restrict__ g,
    const float* __restrict__ b, float* __restrict__ out)
{
    __shared__ float red[8];
    const int row = blockIdx.x, d = threadIdx.x;
    const int lane = d & 31, warp = d >> 5;
    const float v = y[(size_t)row * DD + d];

    float s = v;
#pragma unroll
    for (int off = 16; off; off >>= 1) s += __shfl_xor_sync(0xffffffffu, s, off);
    if (lane == 0) red[warp] = s;
    __syncthreads();
    float tot = red[0] + red[1] + red[2] + red[3] + red[4] + red[5] + red[6] + red[7];
    const float mu = tot * (1.0f / 256.0f);
    const float dv = v - mu;
    __syncthreads();

    float s2 = dv * dv;
#pragma unroll
    for (int off = 16; off; off >>= 1) s2 += __shfl_xor_sync(0xffffffffu, s2, off);
    if (lane == 0) red[warp] = s2;
    __syncthreads();
    float tot2 = red[0] + red[1] + red[2] + red[3] + red[4] + red[5] + red[6] + red[7];
    const float var = tot2 * (1.0f / 256.0f);

    out[(size_t)row * DD + d] = dv * rsqrtf(var + 1e-6f) * g[d] + b[d];
}

// ============================================================================
// host
// ============================================================================
static float* sym_addr(const void* sym) {
    void* p = nullptr;
    cudaGetSymbolAddress(&p, sym);
    return (float*)p;
}

extern "C" void kernel_launch(void* const* d_in, const int* in_sizes, int n_in,
                              void* d_out, int out_size)
{
    (void)n_in; (void)out_size;
    const float *x, *svd, *Wsvd, *bsvd, *ide, *ode, *spe;
    const float *Wq, *bq, *Wk, *bk, *Wv, *bv, *Wa, *ba, *g1, *lb1;
    const float *W1, *b1, *W2, *b2, *g2, *lb2;
    const int *ind, *outd, *spp;

    auto F = [&](int i) { return (const float*)d_in[i]; };
    auto I = [&](int i) { return (const int*)d_in[i]; };

    if (in_sizes[1] == 1024) {
        x = F(0);  ind = I(1); outd = I(2); spp = I(3);
        svd = F(4); ide = F(5); ode = F(6); spe = F(7);
        Wsvd = F(8); bsvd = F(9);
        Wq = F(10); Wk = F(11); Wv = F(12); Wa = F(13); W1 = F(14); W2 = F(15);
        bq = F(16); bk = F(17); bv = F(18); ba = F(19); b1 = F(20); b2 = F(21);
        lb1 = F(22); lb2 = F(23); g1 = F(24); g2 = F(25);
    } else {
        x = F(0); svd = F(1); Wsvd = F(2); bsvd = F(3);
        ide = F(4); ode = F(5); spe = F(6);
        Wq = F(7); bq = F(8); Wk = F(9); bk = F(10); Wv = F(11); bv = F(12);
        Wa = F(13); ba = F(14); g1 = F(15); lb1 = F(16);
        W1 = F(17); b1 = F(18); W2 = F(19); b2 = F(20); g2 = F(21); lb2 = F(22);
        ind = I(23); outd = I(24); spp = I(25);
    }

    float* h = sym_addr(g_h);
    float* q = sym_addr(g_q);
    float* k = sym_addr(g_k);
    float* v = sym_addr(g_v);
    float* o = sym_addr(g_o);
    float* y = sym_addr(g_y);
    float* f = sym_addr(g_f);
    float* bt = sym_addr(g_bias);
    float* out = (float*)d_out;

    const dim3 ggrid(DD / 64, MTOT / 128);    // (4, 32)
    const dim3 qgrid(12, MTOT / 128);         // fused QKV (12, 32)
    const dim3 agrid(NN / 64, BB * HH);       // (16, 32)

    bias_kernel<<<NN * NN / 256, 256>>>(spp, spe, bt);
    embed_kernel<<<MTOT, 256>>>(x, ind, outd, svd, Wsvd, bsvd, ide, ode, h);

    for (int l = 0; l < LL; l++) {
        const size_t wo = (size_t)l * DD * DD;
        const size_t bo = (size_t)l * DD;

        qkv_kernel<<<qgrid, 256>>>(h, Wq + wo, Wk + wo, Wv + wo,
                                   bq + bo, bk + bo, bv + bo, q, k, v);

        attn_kernel<<<agrid, 256>>>(q, k, v, bt, o);

        gemm_kernel<2><<<ggrid, 256>>>(o, Wa + wo, ba + bo, h, y);
        ln_kernel<<<MTOT, 256>>>(y, g1 + bo, lb1 + bo, h);

        gemm_kernel<1><<<ggrid, 256>>>(h, W1 + wo, b1 + bo, nullptr, f);
        gemm_kernel<2><<<ggrid, 256>>>(f, W2 + wo, b2 + bo, h, y);

        float* dst = (l == LL - 1) ? out : h;
        ln_kernel<<<MTOT, 256>>>(y, g2 + bo, lb2 + bo, dst);
    }
}

// round 9
// speedup vs baseline: 1.9674x; 1.4784x over previous
#include <cuda_runtime.h>
#include <cstdint>

#define BB 4
#define NN 1024
#define HH 8
#define DD 256
#define LL 4
#define MTOT (BB * NN)  // 4096

typedef unsigned long long ull;
typedef unsigned int uint;

// ---------------- packed fp32x2 helpers (sm_103a FFMA2) ----------------
__device__ __forceinline__ ull f2fma(ull a, ull b, ull c) {
    ull d; asm("fma.rn.f32x2 %0, %1, %2, %3;" : "=l"(d) : "l"(a), "l"(b), "l"(c)); return d;
}
__device__ __forceinline__ ull fdup(float x) {
    ull d; unsigned r = __float_as_uint(x);
    asm("mov.b64 %0, {%1, %1};" : "=l"(d) : "r"(r)); return d;
}
__device__ __forceinline__ float2 f2unp(ull v) {
    unsigned lo, hi; asm("mov.b64 {%0, %1}, %2;" : "=r"(lo), "=r"(hi) : "l"(v));
    return make_float2(__uint_as_float(lo), __uint_as_float(hi));
}

// ---------------- tf32 helpers ----------------
__device__ __forceinline__ float tf32r(float x) {
    uint r; asm("cvt.rna.tf32.f32 %0, %1;" : "=r"(r) : "f"(x));
    return __uint_as_float(r);
}
// D += A(16x8,row) * B(8x8,col), tf32 inputs, f32 accum
__device__ __forceinline__ void mma_tf32(float c[4], const uint a[4], uint b0, uint b1) {
    asm("mma.sync.aligned.m16n8k8.row.col.f32.tf32.tf32.f32 "
        "{%0,%1,%2,%3}, {%4,%5,%6,%7}, {%8,%9}, {%0,%1,%2,%3};"
        : "+f"(c[0]), "+f"(c[1]), "+f"(c[2]), "+f"(c[3])
        : "r"(a[0]), "r"(a[1]), "r"(a[2]), "r"(a[3]), "r"(b0), "r"(b1));
}

// ---------------- scratch buffers ----------------
__device__ float g_h[MTOT * DD];
__device__ float g_q[MTOT * DD];
__device__ float g_k[MTOT * DD];
__device__ float g_v[MTOT * DD];
__device__ float g_o[MTOT * DD];
__device__ float g_y[MTOT * DD];
__device__ float g_f[MTOT * DD];
__device__ float g_bias[HH * NN * NN];   // 32MB precomputed attention bias [h][q][k]

// ============================================================================
// bias precompute: bias[h][q][k] = spe[spp[q][k]*H + h]
// ============================================================================
__global__ void __launch_bounds__(256) bias_kernel(
    const int* __restrict__ spp, const float* __restrict__ spe,
    float* __restrict__ bias)
{
    const int idx = blockIdx.x * 256 + threadIdx.x;   // over N*N
    const int sp = spp[idx];
    const float4 e0 = *(const float4*)&spe[sp * 8];
    const float4 e1 = *(const float4*)&spe[sp * 8 + 4];
    bias[0 * NN * NN + idx] = e0.x;
    bias[1 * NN * NN + idx] = e0.y;
    bias[2 * NN * NN + idx] = e0.z;
    bias[3 * NN * NN + idx] = e0.w;
    bias[4 * NN * NN + idx] = e1.x;
    bias[5 * NN * NN + idx] = e1.y;
    bias[6 * NN * NN + idx] = e1.z;
    bias[7 * NN * NN + idx] = e1.w;
}

// ============================================================================
// embed
// ============================================================================
__global__ void __launch_bounds__(256) embed_kernel(
    const float* __restrict__ x, const int* __restrict__ ind,
    const int* __restrict__ outd, const float* __restrict__ svd,
    const float* __restrict__ Wsvd, const float* __restrict__ bsvd,
    const float* __restrict__ ide, const float* __restrict__ ode,
    float* __restrict__ h)
{
    int bn = blockIdx.x;
    int n  = bn & (NN - 1);
    int d  = threadIdx.x;
    __shared__ float pos[32];
    if (d < 32) {
        float v = svd[n * 32 + d];
        pos[d] = (d < 16) ? v : -v;
    }
    __syncthreads();
    int di = ind[n], do2 = outd[n];
    float acc = x[(size_t)bn * DD + d]
              + ide[(size_t)di * DD + d]
              + ode[(size_t)do2 * DD + d]
              + bsvd[d];
#pragma unroll
    for (int k = 0; k < 32; k++)
        acc = fmaf(pos[k], Wsvd[k * DD + d], acc);
    h[(size_t)bn * DD + d] = acc;
}

// ============================================================================
// GEMM core: 128x64 tile, K-chunks of 32, register-prefetched global loads,
// fp32x2 packed FMA micro-kernel (8 rows x 2 pairs per thread).
// EPI: 0 = bias, 1 = bias+relu, 2 = bias+residual
// ============================================================================
template <int EPI>
__device__ __forceinline__ void gemm_core(
    const float* __restrict__ X, const float* __restrict__ W,
    const float* __restrict__ bias, const float* __restrict__ res,
    float* __restrict__ Y, const int m0, const int n0)
{
    __shared__ __align__(16) float As[32][132];  // [k][m], 128+4 pad
    __shared__ __align__(16) float Bs[32][64];   // [k][n]
    const int tid = threadIdx.x;
    const int tx = tid & 15, ty = tid >> 4;
    const int lr = tid >> 1;
    const int lc = (tid & 1) << 4;
    const int wr = tid >> 3;
    const int wc = (tid & 7) << 3;

    float4 xr[4], wv[2];
    {
        const float* Xp = &X[(size_t)(m0 + lr) * DD + lc];
#pragma unroll
        for (int j = 0; j < 4; j++) xr[j] = *(const float4*)(Xp + 4 * j);
        const float* Wp = &W[(size_t)wr * DD + n0 + wc];
        wv[0] = *(const float4*)Wp;
        wv[1] = *(const float4*)(Wp + 4);
    }
#pragma unroll
    for (int j = 0; j < 4; j++) {
        As[lc + 4 * j + 0][lr] = xr[j].x;
        As[lc + 4 * j + 1][lr] = xr[j].y;
        As[lc + 4 * j + 2][lr] = xr[j].z;
        As[lc + 4 * j + 3][lr] = xr[j].w;
    }
    *(float4*)&Bs[wr][wc] = wv[0];
    *(float4*)&Bs[wr][wc + 4] = wv[1];
    __syncthreads();

    ull acc2[8][2] = {};
#pragma unroll 1
    for (int c = 0; c < 8; c++) {
        if (c < 7) {
            const float* Xp = &X[(size_t)(m0 + lr) * DD + (c + 1) * 32 + lc];
#pragma unroll
            for (int j = 0; j < 4; j++) xr[j] = *(const float4*)(Xp + 4 * j);
            const float* Wp = &W[(size_t)((c + 1) * 32 + wr) * DD + n0 + wc];
            wv[0] = *(const float4*)Wp;
            wv[1] = *(const float4*)(Wp + 4);
        }
#pragma unroll
        for (int kk = 0; kk < 32; kk++) {
            const float4 a0 = *(const float4*)&As[kk][ty << 3];
            const float4 a1 = *(const float4*)&As[kk][(ty << 3) + 4];
            const ulonglong2 b2 = *(const ulonglong2*)&Bs[kk][tx << 2];
            const float av[8] = {a0.x, a0.y, a0.z, a0.w, a1.x, a1.y, a1.z, a1.w};
#pragma unroll
            for (int i = 0; i < 8; i++) {
                const ull ad = fdup(av[i]);
                acc2[i][0] = f2fma(ad, b2.x, acc2[i][0]);
                acc2[i][1] = f2fma(ad, b2.y, acc2[i][1]);
            }
        }
        __syncthreads();
        if (c < 7) {
#pragma unroll
            for (int j = 0; j < 4; j++) {
                As[lc + 4 * j + 0][lr] = xr[j].x;
                As[lc + 4 * j + 1][lr] = xr[j].y;
                As[lc + 4 * j + 2][lr] = xr[j].z;
                As[lc + 4 * j + 3][lr] = xr[j].w;
            }
            *(float4*)&Bs[wr][wc] = wv[0];
            *(float4*)&Bs[wr][wc + 4] = wv[1];
            __syncthreads();
        }
    }

    const float4 bb = *(const float4*)&bias[n0 + (tx << 2)];
#pragma unroll
    for (int i = 0; i < 8; i++) {
        const int row = m0 + (ty << 3) + i;
        const float2 a01 = f2unp(acc2[i][0]);
        const float2 a23 = f2unp(acc2[i][1]);
        float4 o;
        o.x = a01.x + bb.x; o.y = a01.y + bb.y;
        o.z = a23.x + bb.z; o.w = a23.y + bb.w;
        if (EPI == 2) {
            const float4 r4 = *(const float4*)&res[(size_t)row * DD + n0 + (tx << 2)];
            o.x += r4.x; o.y += r4.y; o.z += r4.z; o.w += r4.w;
        }
        if (EPI == 1) {
            o.x = fmaxf(o.x, 0.f); o.y = fmaxf(o.y, 0.f);
            o.z = fmaxf(o.z, 0.f); o.w = fmaxf(o.w, 0.f);
        }
        *(float4*)&Y[(size_t)row * DD + n0 + (tx << 2)] = o;
    }
}

template <int EPI>
__global__ void __launch_bounds__(256) gemm_kernel(
    const float* __restrict__ X, const float* __restrict__ W,
    const float* __restrict__ bias, const float* __restrict__ res,
    float* __restrict__ Y)
{
    gemm_core<EPI>(X, W, bias, res, Y, blockIdx.y << 7, blockIdx.x << 6);
}

__global__ void __launch_bounds__(256) qkv_kernel(
    const float* __restrict__ h,
    const float* __restrict__ Wq, const float* __restrict__ Wk, const float* __restrict__ Wv,
    const float* __restrict__ bq, const float* __restrict__ bk, const float* __restrict__ bv,
    float* __restrict__ q, float* __restrict__ k, float* __restrict__ v)
{
    const int sel = blockIdx.x >> 2;
    const int n0 = (blockIdx.x & 3) << 6;
    const int m0 = blockIdx.y << 7;
    const float* W = (sel == 0) ? Wq : (sel == 1) ? Wk : Wv;
    const float* B = (sel == 0) ? bq : (sel == 1) ? bk : bv;
    float* Y       = (sel == 0) ? q  : (sel == 1) ? k  : v;
    gemm_core<0>(h, W, B, nullptr, Y, m0, n0);
}

// ============================================================================
// Flash attention with tf32 mma.sync (m16n8k8) for both QK^T and PV.
// No-max softmax (scores tiny). Q pre-scaled+tf32 in smem.
// Warp layout: wq = warp&3 -> 16 q-rows; wn = warp>>2 -> key half (QK) /
// dk half (PV). PV accumulators persist in registers across all 16 k-tiles.
// grid (16 q-tiles, 32 bh), 256 threads.
// ============================================================================
__global__ void __launch_bounds__(256) attn_kernel(
    const float* __restrict__ Q, const float* __restrict__ K,
    const float* __restrict__ V, const float* __restrict__ bias,
    float* __restrict__ O)
{
    __shared__ __align__(16) float Qs[64][36];   // [q][dk]   tf32(Q*scale)
    __shared__ __align__(16) float Ks[64][36];   // [key][dk] tf32
    __shared__ __align__(16) float Vt[32][68];   // [dk][key] tf32
    __shared__ __align__(16) float Ps[64][68];   // [q][key]  tf32(P)  (64 cols + pad)
    __shared__ float lsm[64][2];

    const int tid  = threadIdx.x;
    const int lane = tid & 31, warp = tid >> 5;
    const int wq = warp & 3;        // q-row block of 16
    const int wn = warp >> 2;       // half selector
    const int gID = lane >> 2, tig = lane & 3;
    const int q0 = blockIdx.x << 6;
    const int bh = blockIdx.y;
    const int b  = bh >> 3, h = bh & 7;
    const float scale = 0.17677669529663687f;    // 1/sqrt(32)
    const float* __restrict__ bias_h = bias + ((size_t)h << 20);

    // ---- load Q tile: scale + tf32, layout [q][dk] pad 36 ----
#pragma unroll
    for (int i = tid; i < 512; i += 256) {
        const int r = i >> 3, c = (i & 7) << 2;
        const float4 v4 = *(const float4*)&Q[(((size_t)b * NN + q0 + r) << 8) + (h << 5) + c];
        Qs[r][c + 0] = tf32r(v4.x * scale);
        Qs[r][c + 1] = tf32r(v4.y * scale);
        Qs[r][c + 2] = tf32r(v4.z * scale);
        Qs[r][c + 3] = tf32r(v4.w * scale);
    }
    // ---- K/V tile 0 ----
    {
        const int r = tid >> 3, c = (tid & 7) << 2;
        const size_t base = (((size_t)b * NN + r) << 8) + (h << 5) + c;
        const float4 k4 = *(const float4*)&K[base];
        const float4 v4 = *(const float4*)&V[base];
        float4 kc = make_float4(tf32r(k4.x), tf32r(k4.y), tf32r(k4.z), tf32r(k4.w));
        *(float4*)&Ks[r][c] = kc;
        Vt[c + 0][r] = tf32r(v4.x); Vt[c + 1][r] = tf32r(v4.y);
        Vt[c + 2][r] = tf32r(v4.z); Vt[c + 3][r] = tf32r(v4.w);
        const size_t base1 = base + (32 << 8);   // rows 32..63
        const float4 k5 = *(const float4*)&K[base1];
        const float4 v5 = *(const float4*)&V[base1];
        float4 kd = make_float4(tf32r(k5.x), tf32r(k5.y), tf32r(k5.z), tf32r(k5.w));
        *(float4*)&Ks[r + 32][c] = kd;
        Vt[c + 0][r + 32] = tf32r(v5.x); Vt[c + 1][r + 32] = tf32r(v5.y);
        Vt[c + 2][r + 32] = tf32r(v5.z); Vt[c + 3][r + 32] = tf32r(v5.w);
    }
    __syncthreads();

    float oacc[2][4] = {};      // PV accumulators: [ntile(dk 8)][frag]
    float lpA = 0.f, lpB = 0.f; // row-sum partials (rows gID, gID+8 of wq block)

    const int rowA = wq * 16 + gID;     // smem q row for a0/a2 frags

#pragma unroll 1
    for (int t = 0; t < 16; t++) {
        // prefetch next K/V tile into registers
        float4 kp0, kp1, vp0, vp1;
        if (t < 15) {
            const int r = tid >> 3, c = (tid & 7) << 2;
            const size_t base = (((size_t)b * NN + (t + 1) * 64 + r) << 8) + (h << 5) + c;
            kp0 = *(const float4*)&K[base];
            vp0 = *(const float4*)&V[base];
            kp1 = *(const float4*)&K[base + (32 << 8)];
            vp1 = *(const float4*)&V[base + (32 << 8)];
        }

        // ---- QK: S[16q x 32k] per warp, 4 ksteps x 4 ntiles ----
        float c4[4][4] = {};
#pragma unroll
        for (int s = 0; s < 4; s++) {
            uint a[4];
            a[0] = __float_as_uint(Qs[rowA][8 * s + tig]);
            a[1] = __float_as_uint(Qs[rowA + 8][8 * s + tig]);
            a[2] = __float_as_uint(Qs[rowA][8 * s + tig + 4]);
            a[3] = __float_as_uint(Qs[rowA + 8][8 * s + tig + 4]);
#pragma unroll
            for (int nt = 0; nt < 4; nt++) {
                const int key = wn * 32 + nt * 8 + gID;
                const uint b0 = __float_as_uint(Ks[key][8 * s + tig]);
                const uint b1 = __float_as_uint(Ks[key][8 * s + tig + 4]);
                mma_tf32(c4[nt], a, b0, b1);
            }
        }

        // ---- epilogue: +bias, exp, l partials, tf32 P ----
        float2 pA[4], pB[4];
        {
            const int qgA = q0 + rowA;
            const int colb = t * 64 + wn * 32 + 2 * tig;
#pragma unroll
            for (int nt = 0; nt < 4; nt++) {
                const float2 bbA = *(const float2*)&bias_h[((size_t)qgA << 10) + colb + nt * 8];
                const float2 bbB = *(const float2*)&bias_h[((size_t)(qgA + 8) << 10) + colb + nt * 8];
                float p0 = __expf(c4[nt][0] + bbA.x);
                float p1 = __expf(c4[nt][1] + bbA.y);
                float p2 = __expf(c4[nt][2] + bbB.x);
                float p3 = __expf(c4[nt][3] + bbB.y);
                lpA += p0 + p1; lpB += p2 + p3;
                pA[nt] = make_float2(tf32r(p0), tf32r(p1));
                pB[nt] = make_float2(tf32r(p2), tf32r(p3));
            }
        }

        __syncthreads();   // all QK reads of Ks done; prev PV reads of Ps done

        // store P, store next K
        {
            const int colL = wn * 32 + 2 * tig;
#pragma unroll
            for (int nt = 0; nt < 4; nt++) {
                *(float2*)&Ps[rowA][colL + nt * 8] = pA[nt];
                *(float2*)&Ps[rowA + 8][colL + nt * 8] = pB[nt];
            }
        }
        if (t < 15) {
            const int r = tid >> 3, c = (tid & 7) << 2;
            float4 kc = make_float4(tf32r(kp0.x), tf32r(kp0.y), tf32r(kp0.z), tf32r(kp0.w));
            *(float4*)&Ks[r][c] = kc;
            float4 kd = make_float4(tf32r(kp1.x), tf32r(kp1.y), tf32r(kp1.z), tf32r(kp1.w));
            *(float4*)&Ks[r + 32][c] = kd;
        }
        __syncthreads();   // Ps (+ next Ks) visible

        // ---- PV: O[16q x 16dk] per warp, 8 ksteps x 2 ntiles ----
#pragma unroll
        for (int s = 0; s < 8; s++) {
            uint a[4];
            a[0] = __float_as_uint(Ps[rowA][8 * s + tig]);
            a[1] = __float_as_uint(Ps[rowA + 8][8 * s + tig]);
            a[2] = __float_as_uint(Ps[rowA][8 * s + tig + 4]);
            a[3] = __float_as_uint(Ps[rowA + 8][8 * s + tig + 4]);
#pragma unroll
            for (int nt = 0; nt < 2; nt++) {
                const int dk = wn * 16 + nt * 8 + gID;
                const uint b0 = __float_as_uint(Vt[dk][8 * s + tig]);
                const uint b1 = __float_as_uint(Vt[dk][8 * s + tig + 4]);
                mma_tf32(oacc[nt], a, b0, b1);
            }
        }
        __syncthreads();   // PV reads of Vt/Ps done

        if (t < 15) {
            const int r = tid >> 3, c = (tid & 7) << 2;
            Vt[c + 0][r] = tf32r(vp0.x); Vt[c + 1][r] = tf32r(vp0.y);
            Vt[c + 2][r] = tf32r(vp0.z); Vt[c + 3][r] = tf32r(vp0.w);
            Vt[c + 0][r + 32] = tf32r(vp1.x); Vt[c + 1][r + 32] = tf32r(vp1.y);
            Vt[c + 2][r + 32] = tf32r(vp1.z); Vt[c + 3][r + 32] = tf32r(vp1.w);
        }
        // next iteration's first __syncthreads orders these stores before PV
    }

    // ---- row sums: reduce over the 4 lanes of each quad (cols) ----
    lpA += __shfl_xor_sync(0xffffffffu, lpA, 1);
    lpA += __shfl_xor_sync(0xffffffffu, lpA, 2);
    lpB += __shfl_xor_sync(0xffffffffu, lpB, 1);
    lpB += __shfl_xor_sync(0xffffffffu, lpB, 2);
    __syncthreads();   // Vt stores from last iter done; safe to write lsm
    if (tig == 0) {
        lsm[rowA][wn] = lpA;
        lsm[rowA + 8][wn] = lpB;
    }
    __syncthreads();

    const float2 lA2 = *(const float2*)&lsm[rowA][0];
    const float2 lB2 = *(const float2*)&lsm[rowA + 8][0];
    const float lA = lA2.x + lA2.y;
    const float lB = lB2.x + lB2.y;

    // ---- write O ----
    {
        const int rgA = q0 + rowA;
        const int col = (h << 5) + wn * 16 + 2 * tig;
#pragma unroll
        for (int nt = 0; nt < 2; nt++) {
            float2 oA = make_float2(oacc[nt][0] / lA, oacc[nt][1] / lA);
            float2 oB = make_float2(oacc[nt][2] / lB, oacc[nt][3] / lB);
            *(float2*)&O[(((size_t)b * NN + rgA) << 8) + col + nt * 8] = oA;
            *(float2*)&O[(((size_t)b * NN + rgA + 8) << 8) + col + nt * 8] = oB;
        }
    }
}

// ============================================================================
// LayerNorm over last dim (256)
// ============================================================================
__global__ void __launch_bounds__(256) ln_kernel(
    const float* __restrict__ y, const float* __restrict__ g,
    const float* __restrict__ b, float* __restrict__ out)
{
    __shared__ float red[8];
    const int row = blockIdx.x, d = threadIdx.x;
    const int lane = d & 31, warp = d >> 5;
    const float v = y[(size_t)row * DD + d];

    float s = v;
#pragma unroll
    for (int off = 16; off; off >>= 1) s += __shfl_xor_sync(0xffffffffu, s, off);
    if (lane == 0) red[warp] = s;
    __syncthreads();
    float tot = red[0] + red[1] + red[2] + red[3] + red[4] + red[5] + red[6] + red[7];
    const float mu = tot * (1.0f / 256.0f);
    const float dv = v - mu;
    __syncthreads();

    float s2 = dv * dv;
#pragma unroll
    for (int off = 16; off; off >>= 1) s2 += __shfl_xor_sync(0xffffffffu, s2, off);
    if (lane == 0) red[warp] = s2;
    __syncthreads();
    float tot2 = red[0] + red[1] + red[2] + red[3] + red[4] + red[5] + red[6] + red[7];
    const float var = tot2 * (1.0f / 256.0f);

    out[(size_t)row * DD + d] = dv * rsqrtf(var + 1e-6f) * g[d] + b[d];
}

// ============================================================================
// host
// ============================================================================
static float* sym_addr(const void* sym) {
    void* p = nullptr;
    cudaGetSymbolAddress(&p, sym);
    return (float*)p;
}

extern "C" void kernel_launch(void* const* d_in, const int* in_sizes, int n_in,
                              void* d_out, int out_size)
{
    (void)n_in; (void)out_size;
    const float *x, *svd, *Wsvd, *bsvd, *ide, *ode, *spe;
    const float *Wq, *bq, *Wk, *bk, *Wv, *bv, *Wa, *ba, *g1, *lb1;
    const float *W1, *b1, *W2, *b2, *g2, *lb2;
    const int *ind, *outd, *spp;

    auto F = [&](int i) { return (const float*)d_in[i]; };
    auto I = [&](int i) { return (const int*)d_in[i]; };

    if (in_sizes[1] == 1024) {
        x = F(0);  ind = I(1); outd = I(2); spp = I(3);
        svd = F(4); ide = F(5); ode = F(6); spe = F(7);
        Wsvd = F(8); bsvd = F(9);
        Wq = F(10); Wk = F(11); Wv = F(12); Wa = F(13); W1 = F(14); W2 = F(15);
        bq = F(16); bk = F(17); bv = F(18); ba = F(19); b1 = F(20); b2 = F(21);
        lb1 = F(22); lb2 = F(23); g1 = F(24); g2 = F(25);
    } else {
        x = F(0); svd = F(1); Wsvd = F(2); bsvd = F(3);
        ide = F(4); ode = F(5); spe = F(6);
        Wq = F(7); bq = F(8); Wk = F(9); bk = F(10); Wv = F(11); bv = F(12);
        Wa = F(13); ba = F(14); g1 = F(15); lb1 = F(16);
        W1 = F(17); b1 = F(18); W2 = F(19); b2 = F(20); g2 = F(21); lb2 = F(22);
        ind = I(23); outd = I(24); spp = I(25);
    }

    float* h = sym_addr(g_h);
    float* q = sym_addr(g_q);
    float* k = sym_addr(g_k);
    float* v = sym_addr(g_v);
    float* o = sym_addr(g_o);
    float* y = sym_addr(g_y);
    float* f = sym_addr(g_f);
    float* bt = sym_addr(g_bias);
    float* out = (float*)d_out;

    const dim3 ggrid(DD / 64, MTOT / 128);    // (4, 32)
    const dim3 qgrid(12, MTOT / 128);         // fused QKV (12, 32)
    const dim3 agrid(NN / 64, BB * HH);       // (16, 32)

    bias_kernel<<<NN * NN / 256, 256>>>(spp, spe, bt);
    embed_kernel<<<MTOT, 256>>>(x, ind, outd, svd, Wsvd, bsvd, ide, ode, h);

    for (int l = 0; l < LL; l++) {
        const size_t wo = (size_t)l * DD * DD;
        const size_t bo = (size_t)l * DD;

        qkv_kernel<<<qgrid, 256>>>(h, Wq + wo, Wk + wo, Wv + wo,
                                   bq + bo, bk + bo, bv + bo, q, k, v);

        attn_kernel<<<agrid, 256>>>(q, k, v, bt, o);

        gemm_kernel<2><<<ggrid, 256>>>(o, Wa + wo, ba + bo, h, y);
        ln_kernel<<<MTOT, 256>>>(y, g1 + bo, lb1 + bo, h);

        gemm_kernel<1><<<ggrid, 256>>>(h, W1 + wo, b1 + bo, nullptr, f);
        gemm_kernel<2><<<ggrid, 256>>>(f, W2 + wo, b2 + bo, h, y);

        float* dst = (l == LL - 1) ? out : h;
        ln_kernel<<<MTOT, 256>>>(y, g2 + bo, lb2 + bo, dst);
    }
}

// round 10
// speedup vs baseline: 2.3232x; 1.1809x over previous
#include <cuda_runtime.h>
#include <cuda_fp16.h>
#include <cstdint>

#define BB 4
#define NN 1024
#define HH 8
#define DD 256
#define LL 4
#define MTOT (BB * NN)  // 4096

typedef unsigned long long ull;
typedef unsigned int uint;

// ---------------- packed fp32x2 helpers (sm_103a FFMA2) ----------------
__device__ __forceinline__ ull f2fma(ull a, ull b, ull c) {
    ull d; asm("fma.rn.f32x2 %0, %1, %2, %3;" : "=l"(d) : "l"(a), "l"(b), "l"(c)); return d;
}
__device__ __forceinline__ ull fdup(float x) {
    ull d; unsigned r = __float_as_uint(x);
    asm("mov.b64 %0, {%1, %1};" : "=l"(d) : "r"(r)); return d;
}
__device__ __forceinline__ float2 f2unp(ull v) {
    unsigned lo, hi; asm("mov.b64 {%0, %1}, %2;" : "=r"(lo), "=r"(hi) : "l"(v));
    return make_float2(__uint_as_float(lo), __uint_as_float(hi));
}

// ---------------- fp16 mma helpers ----------------
__device__ __forceinline__ uint h2pack(float lo, float hi) {
    __half2 h = __floats2half2_rn(lo, hi);
    return *(uint*)&h;
}
// D += A(16x16,row) * B(16x8,col), f16 inputs, f32 accum
__device__ __forceinline__ void mma_f16(float c[4], uint a0, uint a1, uint a2, uint a3,
                                        uint b0, uint b1) {
    asm("mma.sync.aligned.m16n8k16.row.col.f32.f16.f16.f32 "
        "{%0,%1,%2,%3}, {%4,%5,%6,%7}, {%8,%9}, {%0,%1,%2,%3};"
        : "+f"(c[0]), "+f"(c[1]), "+f"(c[2]), "+f"(c[3])
        : "r"(a0), "r"(a1), "r"(a2), "r"(a3), "r"(b0), "r"(b1));
}

// ---------------- scratch buffers ----------------
__device__ float g_h[MTOT * DD];
__device__ float g_q[MTOT * DD];
__device__ float g_k[MTOT * DD];
__device__ float g_v[MTOT * DD];
__device__ float g_o[MTOT * DD];
__device__ float g_y[MTOT * DD];
__device__ float g_f[MTOT * DD];
__device__ float g_bias[HH * NN * NN];   // 32MB precomputed attention bias [h][q][k]

// ============================================================================
// bias precompute: bias[h][q][k] = spe[spp[q][k]*H + h]
// ============================================================================
__global__ void __launch_bounds__(256) bias_kernel(
    const int* __restrict__ spp, const float* __restrict__ spe,
    float* __restrict__ bias)
{
    const int idx = blockIdx.x * 256 + threadIdx.x;   // over N*N
    const int sp = spp[idx];
    const float4 e0 = *(const float4*)&spe[sp * 8];
    const float4 e1 = *(const float4*)&spe[sp * 8 + 4];
    bias[0 * NN * NN + idx] = e0.x;
    bias[1 * NN * NN + idx] = e0.y;
    bias[2 * NN * NN + idx] = e0.z;
    bias[3 * NN * NN + idx] = e0.w;
    bias[4 * NN * NN + idx] = e1.x;
    bias[5 * NN * NN + idx] = e1.y;
    bias[6 * NN * NN + idx] = e1.z;
    bias[7 * NN * NN + idx] = e1.w;
}

// ============================================================================
// embed
// ============================================================================
__global__ void __launch_bounds__(256) embed_kernel(
    const float* __restrict__ x, const int* __restrict__ ind,
    const int* __restrict__ outd, const float* __restrict__ svd,
    const float* __restrict__ Wsvd, const float* __restrict__ bsvd,
    const float* __restrict__ ide, const float* __restrict__ ode,
    float* __restrict__ h)
{
    int bn = blockIdx.x;
    int n  = bn & (NN - 1);
    int d  = threadIdx.x;
    __shared__ float pos[32];
    if (d < 32) {
        float v = svd[n * 32 + d];
        pos[d] = (d < 16) ? v : -v;
    }
    __syncthreads();
    int di = ind[n], do2 = outd[n];
    float acc = x[(size_t)bn * DD + d]
              + ide[(size_t)di * DD + d]
              + ode[(size_t)do2 * DD + d]
              + bsvd[d];
#pragma unroll
    for (int k = 0; k < 32; k++)
        acc = fmaf(pos[k], Wsvd[k * DD + d], acc);
    h[(size_t)bn * DD + d] = acc;
}

// ============================================================================
// GEMM core: 128x64 tile, fp32x2 packed FMA (unchanged from R8 — passes)
// EPI: 0 = bias, 1 = bias+relu, 2 = bias+residual
// ============================================================================
template <int EPI>
__device__ __forceinline__ void gemm_core(
    const float* __restrict__ X, const float* __restrict__ W,
    const float* __restrict__ bias, const float* __restrict__ res,
    float* __restrict__ Y, const int m0, const int n0)
{
    __shared__ __align__(16) float As[32][132];
    __shared__ __align__(16) float Bs[32][64];
    const int tid = threadIdx.x;
    const int tx = tid & 15, ty = tid >> 4;
    const int lr = tid >> 1;
    const int lc = (tid & 1) << 4;
    const int wr = tid >> 3;
    const int wc = (tid & 7) << 3;

    float4 xr[4], wv[2];
    {
        const float* Xp = &X[(size_t)(m0 + lr) * DD + lc];
#pragma unroll
        for (int j = 0; j < 4; j++) xr[j] = *(const float4*)(Xp + 4 * j);
        const float* Wp = &W[(size_t)wr * DD + n0 + wc];
        wv[0] = *(const float4*)Wp;
        wv[1] = *(const float4*)(Wp + 4);
    }
#pragma unroll
    for (int j = 0; j < 4; j++) {
        As[lc + 4 * j + 0][lr] = xr[j].x;
        As[lc + 4 * j + 1][lr] = xr[j].y;
        As[lc + 4 * j + 2][lr] = xr[j].z;
        As[lc + 4 * j + 3][lr] = xr[j].w;
    }
    *(float4*)&Bs[wr][wc] = wv[0];
    *(float4*)&Bs[wr][wc + 4] = wv[1];
    __syncthreads();

    ull acc2[8][2] = {};
#pragma unroll 1
    for (int c = 0; c < 8; c++) {
        if (c < 7) {
            const float* Xp = &X[(size_t)(m0 + lr) * DD + (c + 1) * 32 + lc];
#pragma unroll
            for (int j = 0; j < 4; j++) xr[j] = *(const float4*)(Xp + 4 * j);
            const float* Wp = &W[(size_t)((c + 1) * 32 + wr) * DD + n0 + wc];
            wv[0] = *(const float4*)Wp;
            wv[1] = *(const float4*)(Wp + 4);
        }
#pragma unroll
        for (int kk = 0; kk < 32; kk++) {
            const float4 a0 = *(const float4*)&As[kk][ty << 3];
            const float4 a1 = *(const float4*)&As[kk][(ty << 3) + 4];
            const ulonglong2 b2 = *(const ulonglong2*)&Bs[kk][tx << 2];
            const float av[8] = {a0.x, a0.y, a0.z, a0.w, a1.x, a1.y, a1.z, a1.w};
#pragma unroll
            for (int i = 0; i < 8; i++) {
                const ull ad = fdup(av[i]);
                acc2[i][0] = f2fma(ad, b2.x, acc2[i][0]);
                acc2[i][1] = f2fma(ad, b2.y, acc2[i][1]);
            }
        }
        __syncthreads();
        if (c < 7) {
#pragma unroll
            for (int j = 0; j < 4; j++) {
                As[lc + 4 * j + 0][lr] = xr[j].x;
                As[lc + 4 * j + 1][lr] = xr[j].y;
                As[lc + 4 * j + 2][lr] = xr[j].z;
                As[lc + 4 * j + 3][lr] = xr[j].w;
            }
            *(float4*)&Bs[wr][wc] = wv[0];
            *(float4*)&Bs[wr][wc + 4] = wv[1];
            __syncthreads();
        }
    }

    const float4 bb = *(const float4*)&bias[n0 + (tx << 2)];
#pragma unroll
    for (int i = 0; i < 8; i++) {
        const int row = m0 + (ty << 3) + i;
        const float2 a01 = f2unp(acc2[i][0]);
        const float2 a23 = f2unp(acc2[i][1]);
        float4 o;
        o.x = a01.x + bb.x; o.y = a01.y + bb.y;
        o.z = a23.x + bb.z; o.w = a23.y + bb.w;
        if (EPI == 2) {
            const float4 r4 = *(const float4*)&res[(size_t)row * DD + n0 + (tx << 2)];
            o.x += r4.x; o.y += r4.y; o.z += r4.z; o.w += r4.w;
        }
        if (EPI == 1) {
            o.x = fmaxf(o.x, 0.f); o.y = fmaxf(o.y, 0.f);
            o.z = fmaxf(o.z, 0.f); o.w = fmaxf(o.w, 0.f);
        }
        *(float4*)&Y[(size_t)row * DD + n0 + (tx << 2)] = o;
    }
}

template <int EPI>
__global__ void __launch_bounds__(256) gemm_kernel(
    const float* __restrict__ X, const float* __restrict__ W,
    const float* __restrict__ bias, const float* __restrict__ res,
    float* __restrict__ Y)
{
    gemm_core<EPI>(X, W, bias, res, Y, blockIdx.y << 7, blockIdx.x << 6);
}

__global__ void __launch_bounds__(256) qkv_kernel(
    const float* __restrict__ h,
    const float* __restrict__ Wq, const float* __restrict__ Wk, const float* __restrict__ Wv,
    const float* __restrict__ bq, const float* __restrict__ bk, const float* __restrict__ bv,
    float* __restrict__ q, float* __restrict__ k, float* __restrict__ v)
{
    const int sel = blockIdx.x >> 2;
    const int n0 = (blockIdx.x & 3) << 6;
    const int m0 = blockIdx.y << 7;
    const float* W = (sel == 0) ? Wq : (sel == 1) ? Wk : Wv;
    const float* B = (sel == 0) ? bq : (sel == 1) ? bk : bv;
    float* Y       = (sel == 0) ? q  : (sel == 1) ? k  : v;
    gemm_core<0>(h, W, B, nullptr, Y, m0, n0);
}

// ============================================================================
// Flash attention v2: fp16 m16n8k16 MMA, Q fragments in registers,
// S->P->A register chaining (no P smem round trip), double-buffered K/V,
// per-warp key-half O partials merged via smem at the end.
// grid (16 q-tiles, 32 bh), 256 threads (8 warps: wq=warp&3, wn=warp>>2).
// ============================================================================
__global__ void __launch_bounds__(256) attn_kernel(
    const float* __restrict__ Q, const float* __restrict__ K,
    const float* __restrict__ V, const float* __restrict__ bias,
    float* __restrict__ O)
{
    __shared__ __align__(16) __half2 Ks2[2][64][20];  // [buf][key][dk half2] stride 20
    __shared__ __align__(16) __half2 Vp2[2][32][36];  // [buf][key-pair][dk] stride 36
    __shared__ __align__(16) float Osum[64][34];
    __shared__ float lsm[64];

    const int tid  = threadIdx.x;
    const int lane = tid & 31, warp = tid >> 5;
    const int wq = warp & 3;        // q-row block of 16
    const int wn = warp >> 2;       // key half (0: keys 0-31, 1: keys 32-63 of tile)
    const int gID = lane >> 2, tig = lane & 3;
    const int q0 = blockIdx.x << 6;
    const int bh = blockIdx.y;
    const int b  = bh >> 3, h = bh & 7;
    const float scale = 0.17677669529663687f;    // 1/sqrt(32)
    const float* __restrict__ bias_h = bias + ((size_t)h << 20);

    const int rowA = wq * 16 + gID;   // local q rows rowA, rowA+8
    const int qA = q0 + rowA;

    // ---- Q fragments (registers, fixed for whole kernel) ----
    uint qf[2][4];
    {
        const float* QrA = &Q[(((size_t)b * NN + qA) << 8) + (h << 5)];
        const float* QrB = QrA + (8 << 8);
#pragma unroll
        for (int s = 0; s < 2; s++) {
            const float2 f0 = *(const float2*)&QrA[16 * s + 2 * tig];
            const float2 f1 = *(const float2*)&QrB[16 * s + 2 * tig];
            const float2 f2 = *(const float2*)&QrA[16 * s + 2 * tig + 8];
            const float2 f3 = *(const float2*)&QrB[16 * s + 2 * tig + 8];
            qf[s][0] = h2pack(f0.x * scale, f0.y * scale);
            qf[s][1] = h2pack(f1.x * scale, f1.y * scale);
            qf[s][2] = h2pack(f2.x * scale, f2.y * scale);
            qf[s][3] = h2pack(f3.x * scale, f3.y * scale);
        }
    }

    // ---- fill K/V buffer 0 ----
    {
        const int r = tid >> 3, c = (tid & 7) << 2;
        const size_t kb = (((size_t)b * NN + r) << 8) + (h << 5) + c;
        const float4 k0 = *(const float4*)&K[kb];
        const float4 k1 = *(const float4*)&K[kb + (32 << 8)];
        uint2 kk0 = make_uint2(h2pack(k0.x, k0.y), h2pack(k0.z, k0.w));
        uint2 kk1 = make_uint2(h2pack(k1.x, k1.y), h2pack(k1.z, k1.w));
        *(uint2*)&Ks2[0][r][(tid & 7) * 2] = kk0;
        *(uint2*)&Ks2[0][r + 32][(tid & 7) * 2] = kk1;
        const size_t vb = (((size_t)b * NN + 2 * r) << 8) + (h << 5) + c;
        const float4 v0 = *(const float4*)&V[vb];
        const float4 v1 = *(const float4*)&V[vb + (1 << 8)];
        Vp2[0][r][c + 0] = __floats2half2_rn(v0.x, v1.x);
        Vp2[0][r][c + 1] = __floats2half2_rn(v0.y, v1.y);
        Vp2[0][r][c + 2] = __floats2half2_rn(v0.z, v1.z);
        Vp2[0][r][c + 3] = __floats2half2_rn(v0.w, v1.w);
    }
    __syncthreads();

    float oacc[4][4] = {};            // O partial [dk ntile][frag], this warp's key half
    float lpA = 0.f, lpB = 0.f;

#pragma unroll 1
    for (int t = 0; t < 16; t++) {
        const int cur = t & 1, nxt = cur ^ 1;

        // prefetch next K/V tile
        float4 kr0, kr1, vr0, vr1;
        if (t < 15) {
            const int r = tid >> 3, c = (tid & 7) << 2;
            const size_t kb = (((size_t)b * NN + (t + 1) * 64 + r) << 8) + (h << 5) + c;
            kr0 = *(const float4*)&K[kb];
            kr1 = *(const float4*)&K[kb + (32 << 8)];
            const size_t vb = (((size_t)b * NN + (t + 1) * 64 + 2 * r) << 8) + (h << 5) + c;
            vr0 = *(const float4*)&V[vb];
            vr1 = *(const float4*)&V[vb + (1 << 8)];
        }

        // ---- QK: S[16q x 32keys] per warp, 2 ksteps x 4 ntiles ----
        float c4[4][4] = {};
#pragma unroll
        for (int s = 0; s < 2; s++) {
#pragma unroll
            for (int nt = 0; nt < 4; nt++) {
                const int key = wn * 32 + nt * 8 + gID;
                const uint b0 = *(const uint*)&Ks2[cur][key][8 * s + tig];
                const uint b1 = *(const uint*)&Ks2[cur][key][8 * s + 4 + tig];
                mma_f16(c4[nt], qf[s][0], qf[s][1], qf[s][2], qf[s][3], b0, b1);
            }
        }

        // ---- epilogue: +bias, exp, l partials, pack P into PV A-fragments ----
        uint pa[2][4];
        {
            const size_t bA = ((size_t)qA << 10) + t * 64 + wn * 32 + 2 * tig;
#pragma unroll
            for (int nt = 0; nt < 4; nt++) {
                const float2 bbA = *(const float2*)&bias_h[bA + nt * 8];
                const float2 bbB = *(const float2*)&bias_h[bA + (8 << 10) + nt * 8];
                const float p0 = __expf(c4[nt][0] + bbA.x);
                const float p1 = __expf(c4[nt][1] + bbA.y);
                const float p2 = __expf(c4[nt][2] + bbB.x);
                const float p3 = __expf(c4[nt][3] + bbB.y);
                lpA += p0 + p1; lpB += p2 + p3;
                const int u = nt >> 1;
                if ((nt & 1) == 0) { pa[u][0] = h2pack(p0, p1); pa[u][1] = h2pack(p2, p3); }
                else               { pa[u][2] = h2pack(p0, p1); pa[u][3] = h2pack(p2, p3); }
            }
        }

        // ---- PV: O[16q x 32dk] += P[16q x 32keys] * V, 2 ksteps x 4 dk-ntiles ----
#pragma unroll
        for (int u = 0; u < 2; u++) {
            const int kp = wn * 16 + u * 8 + tig;
#pragma unroll
            for (int dnt = 0; dnt < 4; dnt++) {
                const uint b0 = *(const uint*)&Vp2[cur][kp][dnt * 8 + gID];
                const uint b1 = *(const uint*)&Vp2[cur][kp + 4][dnt * 8 + gID];
                mma_f16(oacc[dnt], pa[u][0], pa[u][1], pa[u][2], pa[u][3], b0, b1);
            }
        }

        // ---- store next K/V into the other buffer ----
        if (t < 15) {
            const int r = tid >> 3, c = (tid & 7) << 2;
            uint2 kk0 = make_uint2(h2pack(kr0.x, kr0.y), h2pack(kr0.z, kr0.w));
            uint2 kk1 = make_uint2(h2pack(kr1.x, kr1.y), h2pack(kr1.z, kr1.w));
            *(uint2*)&Ks2[nxt][r][(tid & 7) * 2] = kk0;
            *(uint2*)&Ks2[nxt][r + 32][(tid & 7) * 2] = kk1;
            Vp2[nxt][r][c + 0] = __floats2half2_rn(vr0.x, vr1.x);
            Vp2[nxt][r][c + 1] = __floats2half2_rn(vr0.y, vr1.y);
            Vp2[nxt][r][c + 2] = __floats2half2_rn(vr0.z, vr1.z);
            Vp2[nxt][r][c + 3] = __floats2half2_rn(vr0.w, vr1.w);
        }
        __syncthreads();
    }

    // ---- reduce l over quad lanes (cols) ----
    lpA += __shfl_xor_sync(0xffffffffu, lpA, 1);
    lpA += __shfl_xor_sync(0xffffffffu, lpA, 2);
    lpB += __shfl_xor_sync(0xffffffffu, lpB, 1);
    lpB += __shfl_xor_sync(0xffffffffu, lpB, 2);

    // ---- merge the two key-half O partials via smem ----
    if (wn == 0) {
#pragma unroll
        for (int dnt = 0; dnt < 4; dnt++) {
            *(float2*)&Osum[rowA][dnt * 8 + 2 * tig] = make_float2(oacc[dnt][0], oacc[dnt][1]);
            *(float2*)&Osum[rowA + 8][dnt * 8 + 2 * tig] = make_float2(oacc[dnt][2], oacc[dnt][3]);
        }
        if (tig == 0) { lsm[rowA] = lpA; lsm[rowA + 8] = lpB; }
    }
    __syncthreads();
    if (wn == 1) {
        const float lA = lsm[rowA] + lpA;
        const float lB = lsm[rowA + 8] + lpB;
        const size_t oA = (((size_t)b * NN + qA) << 8) + (h << 5);
        const size_t oB = oA + (8 << 8);
#pragma unroll
        for (int dnt = 0; dnt < 4; dnt++) {
            const int col = dnt * 8 + 2 * tig;
            const float2 s0 = *(const float2*)&Osum[rowA][col];
            const float2 s1 = *(const float2*)&Osum[rowA + 8][col];
            *(float2*)&O[oA + col] = make_float2((s0.x + oacc[dnt][0]) / lA,
                                                 (s0.y + oacc[dnt][1]) / lA);
            *(float2*)&O[oB + col] = make_float2((s1.x + oacc[dnt][2]) / lB,
                                                 (s1.y + oacc[dnt][3]) / lB);
        }
    }
}

// ============================================================================
// LayerNorm over last dim (256)
// ============================================================================
__global__ void __launch_bounds__(256) ln_kernel(
    const float* __restrict__ y, const float* __restrict__ g,
    const float* __restrict__ b, float* __restrict__ out)
{
    __shared__ float red[8];
    const int row = blockIdx.x, d = threadIdx.x;
    const int lane = d & 31, warp = d >> 5;
    const float v = y[(size_t)row * DD + d];

    float s = v;
#pragma unroll
    for (int off = 16; off; off >>= 1) s += __shfl_xor_sync(0xffffffffu, s, off);
    if (lane == 0) red[warp] = s;
    __syncthreads();
    float tot = red[0] + red[1] + red[2] + red[3] + red[4] + red[5] + red[6] + red[7];
    const float mu = tot * (1.0f / 256.0f);
    const float dv = v - mu;
    __syncthreads();

    float s2 = dv * dv;
#pragma unroll
    for (int off = 16; off; off >>= 1) s2 += __shfl_xor_sync(0xffffffffu, s2, off);
    if (lane == 0) red[warp] = s2;
    __syncthreads();
    float tot2 = red[0] + red[1] + red[2] + red[3] + red[4] + red[5] + red[6] + red[7];
    const float var = tot2 * (1.0f / 256.0f);

    out[(size_t)row * DD + d] = dv * rsqrtf(var + 1e-6f) * g[d] + b[d];
}

// ============================================================================
// host
// ============================================================================
static float* sym_addr(const void* sym) {
    void* p = nullptr;
    cudaGetSymbolAddress(&p, sym);
    return (float*)p;
}

extern "C" void kernel_launch(void* const* d_in, const int* in_sizes, int n_in,
                              void* d_out, int out_size)
{
    (void)n_in; (void)out_size;
    const float *x, *svd, *Wsvd, *bsvd, *ide, *ode, *spe;
    const float *Wq, *bq, *Wk, *bk, *Wv, *bv, *Wa, *ba, *g1, *lb1;
    const float *W1, *b1, *W2, *b2, *g2, *lb2;
    const int *ind, *outd, *spp;

    auto F = [&](int i) { return (const float*)d_in[i]; };
    auto I = [&](int i) { return (const int*)d_in[i]; };

    if (in_sizes[1] == 1024) {
        x = F(0);  ind = I(1); outd = I(2); spp = I(3);
        svd = F(4); ide = F(5); ode = F(6); spe = F(7);
        Wsvd = F(8); bsvd = F(9);
        Wq = F(10); Wk = F(11); Wv = F(12); Wa = F(13); W1 = F(14); W2 = F(15);
        bq = F(16); bk = F(17); bv = F(18); ba = F(19); b1 = F(20); b2 = F(21);
        lb1 = F(22); lb2 = F(23); g1 = F(24); g2 = F(25);
    } else {
        x = F(0); svd = F(1); Wsvd = F(2); bsvd = F(3);
        ide = F(4); ode = F(5); spe = F(6);
        Wq = F(7); bq = F(8); Wk = F(9); bk = F(10); Wv = F(11); bv = F(12);
        Wa = F(13); ba = F(14); g1 = F(15); lb1 = F(16);
        W1 = F(17); b1 = F(18); W2 = F(19); b2 = F(20); g2 = F(21); lb2 = F(22);
        ind = I(23); outd = I(24); spp = I(25);
    }

    float* h = sym_addr(g_h);
    float* q = sym_addr(g_q);
    float* k = sym_addr(g_k);
    float* v = sym_addr(g_v);
    float* o = sym_addr(g_o);
    float* y = sym_addr(g_y);
    float* f = sym_addr(g_f);
    float* bt = sym_addr(g_bias);
    float* out = (float*)d_out;

    const dim3 ggrid(DD / 64, MTOT / 128);    // (4, 32)
    const dim3 qgrid(12, MTOT / 128);         // fused QKV (12, 32)
    const dim3 agrid(NN / 64, BB * HH);       // (16, 32)

    bias_kernel<<<NN * NN / 256, 256>>>(spp, spe, bt);
    embed_kernel<<<MTOT, 256>>>(x, ind, outd, svd, Wsvd, bsvd, ide, ode, h);

    for (int l = 0; l < LL; l++) {
        const size_t wo = (size_t)l * DD * DD;
        const size_t bo = (size_t)l * DD;

        qkv_kernel<<<qgrid, 256>>>(h, Wq + wo, Wk + wo, Wv + wo,
                                   bq + bo, bk + bo, bv + bo, q, k, v);

        attn_kernel<<<agrid, 256>>>(q, k, v, bt, o);

        gemm_kernel<2><<<ggrid, 256>>>(o, Wa + wo, ba + bo, h, y);
        ln_kernel<<<MTOT, 256>>>(y, g1 + bo, lb1 + bo, h);

        gemm_kernel<1><<<ggrid, 256>>>(h, W1 + wo, b1 + bo, nullptr, f);
        gemm_kernel<2><<<ggrid, 256>>>(f, W2 + wo, b2 + bo, h, y);

        float* dst = (l == LL - 1) ? out : h;
        ln_kernel<<<MTOT, 256>>>(y, g2 + bo, lb2 + bo, dst);
    }
}

// round 12
// speedup vs baseline: 3.1139x; 1.3404x over previous
#include <cuda_runtime.h>
#include <cuda_fp16.h>
#include <cstdint>

#define BB 4
#define NN 1024
#define HH 8
#define DD 256
#define LL 4
#define MTOT (BB * NN)  // 4096

typedef unsigned long long ull;
typedef unsigned int uint;

// ---------------- fp16 mma helpers ----------------
__device__ __forceinline__ uint h2pack(float lo, float hi) {
    __half2 h = __floats2half2_rn(lo, hi);
    return *(uint*)&h;
}
// D += A(16x16,row) * B(16x8,col), f16 inputs, f32 accum
__device__ __forceinline__ void mma_f16(float c[4], uint a0, uint a1, uint a2, uint a3,
                                        uint b0, uint b1) {
    asm("mma.sync.aligned.m16n8k16.row.col.f32.f16.f16.f32 "
        "{%0,%1,%2,%3}, {%4,%5,%6,%7}, {%8,%9}, {%0,%1,%2,%3};"
        : "+f"(c[0]), "+f"(c[1]), "+f"(c[2]), "+f"(c[3])
        : "r"(a0), "r"(a1), "r"(a2), "r"(a3), "r"(b0), "r"(b1));
}

// ---------------- scratch buffers ----------------
__device__ float g_h[MTOT * DD];
__device__ float g_q[MTOT * DD];
__device__ float g_k[MTOT * DD];
__device__ float g_v[MTOT * DD];
__device__ float g_o[MTOT * DD];
__device__ float g_y[MTOT * DD];
__device__ float g_f[MTOT * DD];
__device__ float g_bias[HH * NN * NN];        // 32MB precomputed attention bias [h][q][k]
__device__ __half g_wh[24 * DD * DD];         // fp16 transposed weights [n][k], 24 mats

// ============================================================================
// weight prep: Wt[(l*6+w)][n][k] = (half) W_w[l][k][n]   (smem tile transpose)
// grid (8, 8, 24), block (32, 8)
// ============================================================================
__global__ void whalf_kernel(
    const float* __restrict__ Wq, const float* __restrict__ Wk,
    const float* __restrict__ Wv, const float* __restrict__ Wa,
    const float* __restrict__ W1, const float* __restrict__ W2,
    __half* __restrict__ out)
{
    __shared__ float t[32][33];
    const int idx = blockIdx.z;
    const int which = idx % 6, layer = idx / 6;
    const float* srcs[6] = {Wq, Wk, Wv, Wa, W1, W2};
    const float* src = srcs[which] + (size_t)layer * DD * DD;
    __half* dst = out + (size_t)idx * DD * DD;

    const int tx = threadIdx.x, ty = threadIdx.y;
#pragma unroll
    for (int i = 0; i < 4; i++) {
        const int k = blockIdx.y * 32 + ty + 8 * i;
        const int n = blockIdx.x * 32 + tx;
        t[ty + 8 * i][tx] = src[k * DD + n];
    }
    __syncthreads();
#pragma unroll
    for (int i = 0; i < 4; i++) {
        const int n = blockIdx.x * 32 + ty + 8 * i;
        const int k = blockIdx.y * 32 + tx;
        dst[n * DD + k] = __float2half(t[tx][ty + 8 * i]);
    }
}

// ============================================================================
// bias precompute: bias[h][q][k] = spe[spp[q][k]*H + h]
// ============================================================================
__global__ void __launch_bounds__(256) bias_kernel(
    const int* __restrict__ spp, const float* __restrict__ spe,
    float* __restrict__ bias)
{
    const int idx = blockIdx.x * 256 + threadIdx.x;   // over N*N
    const int sp = spp[idx];
    const float4 e0 = *(const float4*)&spe[sp * 8];
    const float4 e1 = *(const float4*)&spe[sp * 8 + 4];
    bias[0 * NN * NN + idx] = e0.x;
    bias[1 * NN * NN + idx] = e0.y;
    bias[2 * NN * NN + idx] = e0.z;
    bias[3 * NN * NN + idx] = e0.w;
    bias[4 * NN * NN + idx] = e1.x;
    bias[5 * NN * NN + idx] = e1.y;
    bias[6 * NN * NN + idx] = e1.z;
    bias[7 * NN * NN + idx] = e1.w;
}

// ============================================================================
// embed
// ============================================================================
__global__ void __launch_bounds__(256) embed_kernel(
    const float* __restrict__ x, const int* __restrict__ ind,
    const int* __restrict__ outd, const float* __restrict__ svd,
    const float* __restrict__ Wsvd, const float* __restrict__ bsvd,
    const float* __restrict__ ide, const float* __restrict__ ode,
    float* __restrict__ h)
{
    int bn = blockIdx.x;
    int n  = bn & (NN - 1);
    int d  = threadIdx.x;
    __shared__ float pos[32];
    if (d < 32) {
        float v = svd[n * 32 + d];
        pos[d] = (d < 16) ? v : -v;
    }
    __syncthreads();
    int di = ind[n], do2 = outd[n];
    float acc = x[(size_t)bn * DD + d]
              + ide[(size_t)di * DD + d]
              + ode[(size_t)do2 * DD + d]
              + bsvd[d];
#pragma unroll
    for (int k = 0; k < 32; k++)
        acc = fmaf(pos[k], Wsvd[k * DD + d], acc);
    h[(size_t)bn * DD + d] = acc;
}

// ============================================================================
// fp16 tensor-core GEMM: Y[4096,256] = X @ W + bias (+res) (+relu)
// 128x64 tile, 8 warps (4M x 2N), warp tile 32x32, m16n8k16 MMA.
// X fp32 -> half2 staged per 32-K chunk; W from precomputed fp16 [n][k].
// EPI: 0 = bias, 1 = bias+relu, 2 = bias+residual
// ============================================================================
template <int EPI>
__device__ __forceinline__ void gemm_core_h(
    const float* __restrict__ X, const __half* __restrict__ Wt,
    const float* __restrict__ bias, const float* __restrict__ res,
    float* __restrict__ Y, const int m0, const int n0)
{
    __shared__ __align__(16) __half2 Xs2[128][20];  // [m][k half2] pitch 80B
    __shared__ __align__(16) __half2 Ws2[64][20];   // [n][k half2] pitch 80B

    const int tid = threadIdx.x;
    const int lane = tid & 31, warp = tid >> 5;
    const int wm = warp >> 1, wn = warp & 1;
    const int gID = lane >> 2, tig = lane & 3;

    const int lr = tid >> 1;              // 0..127 X row
    const int lc2 = (tid & 1) << 3;       // half2 col base: 0 or 8
    const int wrow = tid >> 2;            // 0..63 W row (n)
    const int wpart = tid & 3;            // 0..3

    // ---- prologue: chunk 0 ----
    float4 xr[4];
    uint4 wvh;
    {
        const float* Xp = &X[(size_t)(m0 + lr) * DD + (lc2 << 1)];
#pragma unroll
        for (int j = 0; j < 4; j++) xr[j] = *(const float4*)(Xp + 4 * j);
        wvh = *(const uint4*)&Wt[(size_t)(n0 + wrow) * DD + wpart * 8];
    }
#pragma unroll
    for (int j = 0; j < 4; j++) {
        Xs2[lr][lc2 + 2 * j] = __floats2half2_rn(xr[j].x, xr[j].y);
        Xs2[lr][lc2 + 2 * j + 1] = __floats2half2_rn(xr[j].z, xr[j].w);
    }
    *(uint4*)&Ws2[wrow][wpart * 4] = wvh;
    __syncthreads();

    float acc[2][4][4] = {};   // [rowblock][ntile][frag]

#pragma unroll 1
    for (int c = 0; c < 8; c++) {
        if (c < 7) {
            const float* Xp = &X[(size_t)(m0 + lr) * DD + (c + 1) * 32 + (lc2 << 1)];
#pragma unroll
            for (int j = 0; j < 4; j++) xr[j] = *(const float4*)(Xp + 4 * j);
            wvh = *(const uint4*)&Wt[(size_t)(n0 + wrow) * DD + (c + 1) * 32 + wpart * 8];
        }
#pragma unroll
        for (int s = 0; s < 2; s++) {
            uint a[2][4];
#pragma unroll
            for (int rb = 0; rb < 2; rb++) {
                const int base = wm * 32 + rb * 16 + gID;
                a[rb][0] = *(const uint*)&Xs2[base][8 * s + tig];
                a[rb][1] = *(const uint*)&Xs2[base + 8][8 * s + tig];
                a[rb][2] = *(const uint*)&Xs2[base][8 * s + 4 + tig];
                a[rb][3] = *(const uint*)&Xs2[base + 8][8 * s + 4 + tig];
            }
#pragma unroll
            for (int nt = 0; nt < 4; nt++) {
                const int n = wn * 32 + nt * 8 + gID;
                const uint b0 = *(const uint*)&Ws2[n][8 * s + tig];
                const uint b1 = *(const uint*)&Ws2[n][8 * s + 4 + tig];
                mma_f16(acc[0][nt], a[0][0], a[0][1], a[0][2], a[0][3], b0, b1);
                mma_f16(acc[1][nt], a[1][0], a[1][1], a[1][2], a[1][3], b0, b1);
            }
        }
        __syncthreads();
        if (c < 7) {
#pragma unroll
            for (int j = 0; j < 4; j++) {
                Xs2[lr][lc2 + 2 * j] = __floats2half2_rn(xr[j].x, xr[j].y);
                Xs2[lr][lc2 + 2 * j + 1] = __floats2half2_rn(xr[j].z, xr[j].w);
            }
            *(uint4*)&Ws2[wrow][wpart * 4] = wvh;
            __syncthreads();
        }
    }

    // ---- epilogue ----
#pragma unroll
    for (int rb = 0; rb < 2; rb++) {
        const int row0 = m0 + wm * 32 + rb * 16 + gID;
#pragma unroll
        for (int nt = 0; nt < 4; nt++) {
            const int col = n0 + wn * 32 + nt * 8 + 2 * tig;
            const float2 bb = *(const float2*)&bias[col];
            float2 oA = make_float2(acc[rb][nt][0] + bb.x, acc[rb][nt][1] + bb.y);
            float2 oB = make_float2(acc[rb][nt][2] + bb.x, acc[rb][nt][3] + bb.y);
            if (EPI == 2) {
                const float2 rA = *(const float2*)&res[(size_t)row0 * DD + col];
                const float2 rB = *(const float2*)&res[(size_t)(row0 + 8) * DD + col];
                oA.x += rA.x; oA.y += rA.y; oB.x += rB.x; oB.y += rB.y;
            }
            if (EPI == 1) {
                oA.x = fmaxf(oA.x, 0.f); oA.y = fmaxf(oA.y, 0.f);
                oB.x = fmaxf(oB.x, 0.f); oB.y = fmaxf(oB.y, 0.f);
            }
            *(float2*)&Y[(size_t)row0 * DD + col] = oA;
            *(float2*)&Y[(size_t)(row0 + 8) * DD + col] = oB;
        }
    }
}

template <int EPI>
__global__ void __launch_bounds__(256) gemm_kernel(
    const float* __restrict__ X, const __half* __restrict__ Wt,
    const float* __restrict__ bias, const float* __restrict__ res,
    float* __restrict__ Y)
{
    gemm_core_h<EPI>(X, Wt, bias, res, Y, blockIdx.y << 7, blockIdx.x << 6);
}

// fused QKV: grid (12, 32); blockIdx.x>>2 selects Q/K/V, &3 -> n-tile
__global__ void __launch_bounds__(256) qkv_kernel(
    const float* __restrict__ h, const __half* __restrict__ whl,
    const float* __restrict__ bq, const float* __restrict__ bk, const float* __restrict__ bv,
    float* __restrict__ q, float* __restrict__ k, float* __restrict__ v)
{
    const int sel = blockIdx.x >> 2;
    const int n0 = (blockIdx.x & 3) << 6;
    const int m0 = blockIdx.y << 7;
    const __half* Wt = whl + (size_t)sel * DD * DD;
    const float* B = (sel == 0) ? bq : (sel == 1) ? bk : bv;
    float* Y       = (sel == 0) ? q  : (sel == 1) ? k  : v;
    gemm_core_h<0>(h, Wt, B, nullptr, Y, m0, n0);
}

// ============================================================================
// Flash attention v2 (unchanged from R9): fp16 m16n8k16, Q in registers,
// S->P->A register chaining, double-buffered K/V, key-half merge.
// ============================================================================
__global__ void __launch_bounds__(256) attn_kernel(
    const float* __restrict__ Q, const float* __restrict__ K,
    const float* __restrict__ V, const float* __restrict__ bias,
    float* __restrict__ O)
{
    __shared__ __align__(16) __half2 Ks2[2][64][20];
    __shared__ __align__(16) __half2 Vp2[2][32][36];
    __shared__ __align__(16) float Osum[64][34];
    __shared__ float lsm[64];

    const int tid  = threadIdx.x;
    const int lane = tid & 31, warp = tid >> 5;
    const int wq = warp & 3;
    const int wn = warp >> 2;
    const int gID = lane >> 2, tig = lane & 3;
    const int q0 = blockIdx.x << 6;
    const int bh = blockIdx.y;
    const int b  = bh >> 3, h = bh & 7;
    const float scale = 0.17677669529663687f;
    const float* __restrict__ bias_h = bias + ((size_t)h << 20);

    const int rowA = wq * 16 + gID;
    const int qA = q0 + rowA;

    uint qf[2][4];
    {
        const float* QrA = &Q[(((size_t)b * NN + qA) << 8) + (h << 5)];
        const float* QrB = QrA + (8 << 8);
#pragma unroll
        for (int s = 0; s < 2; s++) {
            const float2 f0 = *(const float2*)&QrA[16 * s + 2 * tig];
            const float2 f1 = *(const float2*)&QrB[16 * s + 2 * tig];
            const float2 f2 = *(const float2*)&QrA[16 * s + 2 * tig + 8];
            const float2 f3 = *(const float2*)&QrB[16 * s + 2 * tig + 8];
            qf[s][0] = h2pack(f0.x * scale, f0.y * scale);
            qf[s][1] = h2pack(f1.x * scale, f1.y * scale);
            qf[s][2] = h2pack(f2.x * scale, f2.y * scale);
            qf[s][3] = h2pack(f3.x * scale, f3.y * scale);
        }
    }

    {
        const int r = tid >> 3, c = (tid & 7) << 2;
        const size_t kb = (((size_t)b * NN + r) << 8) + (h << 5) + c;
        const float4 k0 = *(const float4*)&K[kb];
        const float4 k1 = *(const float4*)&K[kb + (32 << 8)];
        uint2 kk0 = make_uint2(h2pack(k0.x, k0.y), h2pack(k0.z, k0.w));
        uint2 kk1 = make_uint2(h2pack(k1.x, k1.y), h2pack(k1.z, k1.w));
        *(uint2*)&Ks2[0][r][(tid & 7) * 2] = kk0;
        *(uint2*)&Ks2[0][r + 32][(tid & 7) * 2] = kk1;
        const size_t vb = (((size_t)b * NN + 2 * r) << 8) + (h << 5) + c;
        const float4 v0 = *(const float4*)&V[vb];
        const float4 v1 = *(const float4*)&V[vb + (1 << 8)];
        Vp2[0][r][c + 0] = __floats2half2_rn(v0.x, v1.x);
        Vp2[0][r][c + 1] = __floats2half2_rn(v0.y, v1.y);
        Vp2[0][r][c + 2] = __floats2half2_rn(v0.z, v1.z);
        Vp2[0][r][c + 3] = __floats2half2_rn(v0.w, v1.w);
    }
    __syncthreads();

    float oacc[4][4] = {};
    float lpA = 0.f, lpB = 0.f;

#pragma unroll 1
    for (int t = 0; t < 16; t++) {
        const int cur = t & 1, nxt = cur ^ 1;

        float4 kr0, kr1, vr0, vr1;
        if (t < 15) {
            const int r = tid >> 3, c = (tid & 7) << 2;
            const size_t kb = (((size_t)b * NN + (t + 1) * 64 + r) << 8) + (h << 5) + c;
            kr0 = *(const float4*)&K[kb];
            kr1 = *(const float4*)&K[kb + (32 << 8)];
            const size_t vb = (((size_t)b * NN + (t + 1) * 64 + 2 * r) << 8) + (h << 5) + c;
            vr0 = *(const float4*)&V[vb];
            vr1 = *(const float4*)&V[vb + (1 << 8)];
        }

        float c4[4][4] = {};
#pragma unroll
        for (int s = 0; s < 2; s++) {
#pragma unroll
            for (int nt = 0; nt < 4; nt++) {
                const int key = wn * 32 + nt * 8 + gID;
                const uint b0 = *(const uint*)&Ks2[cur][key][8 * s + tig];
                const uint b1 = *(const uint*)&Ks2[cur][key][8 * s + 4 + tig];
                mma_f16(c4[nt], qf[s][0], qf[s][1], qf[s][2], qf[s][3], b0, b1);
            }
        }

        uint pa[2][4];
        {
            const size_t bA = ((size_t)qA << 10) + t * 64 + wn * 32 + 2 * tig;
#pragma unroll
            for (int nt = 0; nt < 4; nt++) {
                const float2 bbA = *(const float2*)&bias_h[bA + nt * 8];
                const float2 bbB = *(const float2*)&bias_h[bA + (8 << 10) + nt * 8];
                const float p0 = __expf(c4[nt][0] + bbA.x);
                const float p1 = __expf(c4[nt][1] + bbA.y);
                const float p2 = __expf(c4[nt][2] + bbB.x);
                const float p3 = __expf(c4[nt][3] + bbB.y);
                lpA += p0 + p1; lpB += p2 + p3;
                const int u = nt >> 1;
                if ((nt & 1) == 0) { pa[u][0] = h2pack(p0, p1); pa[u][1] = h2pack(p2, p3); }
                else               { pa[u][2] = h2pack(p0, p1); pa[u][3] = h2pack(p2, p3); }
            }
        }

#pragma unroll
        for (int u = 0; u < 2; u++) {
            const int kp = wn * 16 + u * 8 + tig;
#pragma unroll
            for (int dnt = 0; dnt < 4; dnt++) {
                const uint b0 = *(const uint*)&Vp2[cur][kp][dnt * 8 + gID];
                const uint b1 = *(const uint*)&Vp2[cur][kp + 4][dnt * 8 + gID];
                mma_f16(oacc[dnt], pa[u][0], pa[u][1], pa[u][2], pa[u][3], b0, b1);
            }
        }

        if (t < 15) {
            const int r = tid >> 3, c = (tid & 7) << 2;
            uint2 kk0 = make_uint2(h2pack(kr0.x, kr0.y), h2pack(kr0.z, kr0.w));
            uint2 kk1 = make_uint2(h2pack(kr1.x, kr1.y), h2pack(kr1.z, kr1.w));
            *(uint2*)&Ks2[nxt][r][(tid & 7) * 2] = kk0;
            *(uint2*)&Ks2[nxt][r + 32][(tid & 7) * 2] = kk1;
            Vp2[nxt][r][c + 0] = __floats2half2_rn(vr0.x, vr1.x);
            Vp2[nxt][r][c + 1] = __floats2half2_rn(vr0.y, vr1.y);
            Vp2[nxt][r][c + 2] = __floats2half2_rn(vr0.z, vr1.z);
            Vp2[nxt][r][c + 3] = __floats2half2_rn(vr0.w, vr1.w);
        }
        __syncthreads();
    }

    lpA += __shfl_xor_sync(0xffffffffu, lpA, 1);
    lpA += __shfl_xor_sync(0xffffffffu, lpA, 2);
    lpB += __shfl_xor_sync(0xffffffffu, lpB, 1);
    lpB += __shfl_xor_sync(0xffffffffu, lpB, 2);

    if (wn == 0) {
#pragma unroll
        for (int dnt = 0; dnt < 4; dnt++) {
            *(float2*)&Osum[rowA][dnt * 8 + 2 * tig] = make_float2(oacc[dnt][0], oacc[dnt][1]);
            *(float2*)&Osum[rowA + 8][dnt * 8 + 2 * tig] = make_float2(oacc[dnt][2], oacc[dnt][3]);
        }
        if (tig == 0) { lsm[rowA] = lpA; lsm[rowA + 8] = lpB; }
    }
    __syncthreads();
    if (wn == 1) {
        const float lA = lsm[rowA] + lpA;
        const float lB = lsm[rowA + 8] + lpB;
        const size_t oA = (((size_t)b * NN + qA) << 8) + (h << 5);
        const size_t oB = oA + (8 << 8);
#pragma unroll
        for (int dnt = 0; dnt < 4; dnt++) {
            const int col = dnt * 8 + 2 * tig;
            const float2 s0 = *(const float2*)&Osum[rowA][col];
            const float2 s1 = *(const float2*)&Osum[rowA + 8][col];
            *(float2*)&O[oA + col] = make_float2((s0.x + oacc[dnt][0]) / lA,
                                                 (s0.y + oacc[dnt][1]) / lA);
            *(float2*)&O[oB + col] = make_float2((s1.x + oacc[dnt][2]) / lB,
                                                 (s1.y + oacc[dnt][3]) / lB);
        }
    }
}

// ============================================================================
// LayerNorm over last dim (256)
// ============================================================================
__global__ void __launch_bounds__(256) ln_kernel(
    const float* __restrict__ y, const float* __restrict__ g,
    const float* __restrict__ b, float* __restrict__ out)
{
    __shared__ float red[8];
    const int row = blockIdx.x, d = threadIdx.x;
    const int lane = d & 31, warp = d >> 5;
    const float v = y[(size_t)row * DD + d];

    float s = v;
#pragma unroll
    for (int off = 16; off; off >>= 1) s += __shfl_xor_sync(0xffffffffu, s, off);
    if (lane == 0) red[warp] = s;
    __syncthreads();
    float tot = red[0] + red[1] + red[2] + red[3] + red[4] + red[5] + red[6] + red[7];
    const float mu = tot * (1.0f / 256.0f);
    const float dv = v - mu;
    __syncthreads();

    float s2 = dv * dv;
#pragma unroll
    for (int off = 16; off; off >>= 1) s2 += __shfl_xor_sync(0xffffffffu, s2, off);
    if (lane == 0) red[warp] = s2;
    __syncthreads();
    float tot2 = red[0] + red[1] + red[2] + red[3] + red[4] + red[5] + red[6] + red[7];
    const float var = tot2 * (1.0f / 256.0f);

    out[(size_t)row * DD + d] = dv * rsqrtf(var + 1e-6f) * g[d] + b[d];
}

// ============================================================================
// host
// ============================================================================
static float* sym_addr(const void* sym) {
    void* p = nullptr;
    cudaGetSymbolAddress(&p, sym);
    return (float*)p;
}

extern "C" void kernel_launch(void* const* d_in, const int* in_sizes, int n_in,
                              void* d_out, int out_size)
{
    (void)n_in; (void)out_size;
    const float *x, *svd, *Wsvd, *bsvd, *ide, *ode, *spe;
    const float *Wq, *bq, *Wk, *bk, *Wv, *bv, *Wa, *ba, *g1, *lb1;
    const float *W1, *b1, *W2, *b2, *g2, *lb2;
    const int *ind, *outd, *spp;

    auto F = [&](int i) { return (const float*)d_in[i]; };
    auto I = [&](int i) { return (const int*)d_in[i]; };

    if (in_sizes[1] == 1024) {
        x = F(0);  ind = I(1); outd = I(2); spp = I(3);
        svd = F(4); ide = F(5); ode = F(6); spe = F(7);
        Wsvd = F(8); bsvd = F(9);
        Wq = F(10); Wk = F(11); Wv = F(12); Wa = F(13); W1 = F(14); W2 = F(15);
        bq = F(16); bk = F(17); bv = F(18); ba = F(19); b1 = F(20); b2 = F(21);
        lb1 = F(22); lb2 = F(23); g1 = F(24); g2 = F(25);
    } else {
        x = F(0); svd = F(1); Wsvd = F(2); bsvd = F(3);
        ide = F(4); ode = F(5); spe = F(6);
        Wq = F(7); bq = F(8); Wk = F(9); bk = F(10); Wv = F(11); bv = F(12);
        Wa = F(13); ba = F(14); g1 = F(15); lb1 = F(16);
        W1 = F(17); b1 = F(18); W2 = F(19); b2 = F(20); g2 = F(21); lb2 = F(22);
        ind = I(23); outd = I(24); spp = I(25);
    }

    float* h = sym_addr(g_h);
    float* q = sym_addr(g_q);
    float* k = sym_addr(g_k);
    float* v = sym_addr(g_v);
    float* o = sym_addr(g_o);
    float* y = sym_addr(g_y);
    float* f = sym_addr(g_f);
    float* bt = sym_addr(g_bias);
    __half* wh = (__half*)sym_addr(g_wh);
    float* out = (float*)d_out;

    const dim3 ggrid(DD / 64, MTOT / 128);    // (4, 32)
    const dim3 qgrid(12, MTOT / 128);         // fused QKV (12, 32)
    const dim3 agrid(NN / 64, BB * HH);       // (16, 32)

    whalf_kernel<<<dim3(8, 8, 24), dim3(32, 8)>>>(Wq, Wk, Wv, Wa, W1, W2, wh);
    bias_kernel<<<NN * NN / 256, 256>>>(spp, spe, bt);
    embed_kernel<<<MTOT, 256>>>(x, ind, outd, svd, Wsvd, bsvd, ide, ode, h);

    for (int l = 0; l < LL; l++) {
        const __half* whl = wh + (size_t)l * 6 * DD * DD;
        const size_t bo = (size_t)l * DD;

        qkv_kernel<<<qgrid, 256>>>(h, whl, bq + bo, bk + bo, bv + bo, q, k, v);

        attn_kernel<<<agrid, 256>>>(q, k, v, bt, o);

        gemm_kernel<2><<<ggrid, 256>>>(o, whl + 3 * DD * DD, ba + bo, h, y);
        ln_kernel<<<MTOT, 256>>>(y, g1 + bo, lb1 + bo, h);

        gemm_kernel<1><<<ggrid, 256>>>(h, whl + 4 * DD * DD, b1 + bo, nullptr, f);
        gemm_kernel<2><<<ggrid, 256>>>(f, whl + 5 * DD * DD, b2 + bo, h, y);

        float* dst = (l == LL - 1) ? out : h;
        ln_kernel<<<MTOT, 256>>>(y, g2 + bo, lb2 + bo, dst);
    }
}

// round 15
// speedup vs baseline: 3.8311x; 1.2303x over previous
#include <cuda_runtime.h>
#include <cuda_fp16.h>
#include <cstdint>

#define BB 4
#define NN 1024
#define HH 8
#define DD 256
#define LL 4
#define MTOT (BB * NN)  // 4096

typedef unsigned long long ull;
typedef unsigned int uint;

// ---------------- fp16 mma helpers ----------------
__device__ __forceinline__ uint h2pack(float lo, float hi) {
    __half2 h = __floats2half2_rn(lo, hi);
    return *(uint*)&h;
}
// D += A(16x16,row) * B(16x8,col), f16 inputs, f32 accum
__device__ __forceinline__ void mma_f16(float c[4], uint a0, uint a1, uint a2, uint a3,
                                        uint b0, uint b1) {
    asm("mma.sync.aligned.m16n8k16.row.col.f32.f16.f16.f32 "
        "{%0,%1,%2,%3}, {%4,%5,%6,%7}, {%8,%9}, {%0,%1,%2,%3};"
        : "+f"(c[0]), "+f"(c[1]), "+f"(c[2]), "+f"(c[3])
        : "r"(a0), "r"(a1), "r"(a2), "r"(a3), "r"(b0), "r"(b1));
}

// ---------------- scratch buffers ----------------
__device__ float  g_h[MTOT * DD];
__device__ __half g_h16[MTOT * DD];
__device__ __half g_q[MTOT * DD];
__device__ __half g_k[MTOT * DD];
__device__ __half g_v[MTOT * DD];
__device__ __half g_o[MTOT * DD];
__device__ float  g_y[MTOT * DD];
__device__ __half g_f[MTOT * DD];
__device__ __half g_bias[HH * NN * NN];   // 16MB fp16 attention bias [h][q][k]
__device__ __half g_wh[24 * DD * DD];     // fp16 transposed weights [n][k]

// ============================================================================
// weight prep: Wt[(l*6+w)][n][k] = (half) W_w[l][k][n]
// ============================================================================
__global__ void whalf_kernel(
    const float* __restrict__ Wq, const float* __restrict__ Wk,
    const float* __restrict__ Wv, const float* __restrict__ Wa,
    const float* __restrict__ W1, const float* __restrict__ W2,
    __half* __restrict__ out)
{
    __shared__ float t[32][33];
    const int idx = blockIdx.z;
    const int which = idx % 6, layer = idx / 6;
    const float* srcs[6] = {Wq, Wk, Wv, Wa, W1, W2};
    const float* src = srcs[which] + (size_t)layer * DD * DD;
    __half* dst = out + (size_t)idx * DD * DD;

    const int tx = threadIdx.x, ty = threadIdx.y;
#pragma unroll
    for (int i = 0; i < 4; i++) {
        const int k = blockIdx.y * 32 + ty + 8 * i;
        const int n = blockIdx.x * 32 + tx;
        t[ty + 8 * i][tx] = src[k * DD + n];
    }
    __syncthreads();
#pragma unroll
    for (int i = 0; i < 4; i++) {
        const int n = blockIdx.x * 32 + ty + 8 * i;
        const int k = blockIdx.y * 32 + tx;
        dst[n * DD + k] = __float2half(t[tx][ty + 8 * i]);
    }
}

// ============================================================================
// bias precompute (fp16): bias[h][q][k] = spe[spp[q][k]*H + h]
// ============================================================================
__global__ void __launch_bounds__(256) bias_kernel(
    const int* __restrict__ spp, const float* __restrict__ spe,
    __half* __restrict__ bias)
{
    const int idx = blockIdx.x * 256 + threadIdx.x;   // over N*N
    const int sp = spp[idx];
    const float4 e0 = *(const float4*)&spe[sp * 8];
    const float4 e1 = *(const float4*)&spe[sp * 8 + 4];
    bias[0 * NN * NN + idx] = __float2half(e0.x);
    bias[1 * NN * NN + idx] = __float2half(e0.y);
    bias[2 * NN * NN + idx] = __float2half(e0.z);
    bias[3 * NN * NN + idx] = __float2half(e0.w);
    bias[4 * NN * NN + idx] = __float2half(e1.x);
    bias[5 * NN * NN + idx] = __float2half(e1.y);
    bias[6 * NN * NN + idx] = __float2half(e1.z);
    bias[7 * NN * NN + idx] = __float2half(e1.w);
}

// ============================================================================
// embed (writes fp32 h + fp16 h16)
// ============================================================================
__global__ void __launch_bounds__(256) embed_kernel(
    const float* __restrict__ x, const int* __restrict__ ind,
    const int* __restrict__ outd, const float* __restrict__ svd,
    const float* __restrict__ Wsvd, const float* __restrict__ bsvd,
    const float* __restrict__ ide, const float* __restrict__ ode,
    float* __restrict__ h, __half* __restrict__ h16)
{
    int bn = blockIdx.x;
    int n  = bn & (NN - 1);
    int d  = threadIdx.x;
    __shared__ float pos[32];
    if (d < 32) {
        float v = svd[n * 32 + d];
        pos[d] = (d < 16) ? v : -v;
    }
    __syncthreads();
    int di = ind[n], do2 = outd[n];
    float acc = x[(size_t)bn * DD + d]
              + ide[(size_t)di * DD + d]
              + ode[(size_t)do2 * DD + d]
              + bsvd[d];
#pragma unroll
    for (int k = 0; k < 32; k++)
        acc = fmaf(pos[k], Wsvd[k * DD + d], acc);
    h[(size_t)bn * DD + d] = acc;
    h16[(size_t)bn * DD + d] = __float2half(acc);
}

// ============================================================================
// fp16 tensor-core GEMM: 128x64 tile, double-buffered smem, 1 sync/chunk.
// X fp16 [m][k], W fp16 [n][k]. EPI: 0 bias, 1 bias+relu, 2 bias+res(fp32).
// OUTH: 0 -> fp32 out, 1 -> fp16 out (scaled by oscale).
// ============================================================================
template <int EPI, int OUTH>
__device__ __forceinline__ void gemm_core_h(
    const __half* __restrict__ X, const __half* __restrict__ Wt,
    const float* __restrict__ bias, const float* __restrict__ res,
    void* __restrict__ Yv, const int m0, const int n0, const float oscale)
{
    __shared__ __align__(16) __half2 Xs2[2][128][20];  // pitch 80B
    __shared__ __align__(16) __half2 Ws2[2][64][20];

    const int tid = threadIdx.x;
    const int lane = tid & 31, warp = tid >> 5;
    const int wm = warp >> 1, wn = warp & 1;
    const int gID = lane >> 2, tig = lane & 3;

    const int lr = tid >> 1, lp = tid & 1;   // X: row, 16-half group
    const int wr = tid >> 2, wp = tid & 3;   // W: row, 8-half group

    uint4 xa, xb, wa;
    // ---- stage chunk 0 into buf 0 ----
    {
        const __half* Xp = &X[(size_t)(m0 + lr) * DD + lp * 16];
        xa = *(const uint4*)Xp;
        xb = *(const uint4*)(Xp + 8);
        wa = *(const uint4*)&Wt[(size_t)(n0 + wr) * DD + wp * 8];
    }
    *(uint4*)&Xs2[0][lr][lp * 8] = xa;
    *(uint4*)&Xs2[0][lr][lp * 8 + 4] = xb;
    *(uint4*)&Ws2[0][wr][wp * 4] = wa;
    __syncthreads();

    float acc[2][4][4] = {};

#pragma unroll 1
    for (int c = 0; c < 8; c++) {
        const int cur = c & 1;
        if (c < 7) {
            const __half* Xp = &X[(size_t)(m0 + lr) * DD + (c + 1) * 32 + lp * 16];
            xa = *(const uint4*)Xp;
            xb = *(const uint4*)(Xp + 8);
            wa = *(const uint4*)&Wt[(size_t)(n0 + wr) * DD + (c + 1) * 32 + wp * 8];
        }
#pragma unroll
        for (int s = 0; s < 2; s++) {
            uint a[2][4];
#pragma unroll
            for (int rb = 0; rb < 2; rb++) {
                const int base = wm * 32 + rb * 16 + gID;
                a[rb][0] = *(const uint*)&Xs2[cur][base][8 * s + tig];
                a[rb][1] = *(const uint*)&Xs2[cur][base + 8][8 * s + tig];
                a[rb][2] = *(const uint*)&Xs2[cur][base][8 * s + 4 + tig];
                a[rb][3] = *(const uint*)&Xs2[cur][base + 8][8 * s + 4 + tig];
            }
#pragma unroll
            for (int nt = 0; nt < 4; nt++) {
                const int n = wn * 32 + nt * 8 + gID;
                const uint b0 = *(const uint*)&Ws2[cur][n][8 * s + tig];
                const uint b1 = *(const uint*)&Ws2[cur][n][8 * s + 4 + tig];
                mma_f16(acc[0][nt], a[0][0], a[0][1], a[0][2], a[0][3], b0, b1);
                mma_f16(acc[1][nt], a[1][0], a[1][1], a[1][2], a[1][3], b0, b1);
            }
        }
        if (c < 7) {
            const int nb = cur ^ 1;
            *(uint4*)&Xs2[nb][lr][lp * 8] = xa;
            *(uint4*)&Xs2[nb][lr][lp * 8 + 4] = xb;
            *(uint4*)&Ws2[nb][wr][wp * 4] = wa;
        }
        __syncthreads();
    }

    // ---- epilogue ----
#pragma unroll
    for (int rb = 0; rb < 2; rb++) {
        const int row0 = m0 + wm * 32 + rb * 16 + gID;
#pragma unroll
        for (int nt = 0; nt < 4; nt++) {
            const int col = n0 + wn * 32 + nt * 8 + 2 * tig;
            const float2 bb = *(const float2*)&bias[col];
            float2 oA = make_float2((acc[rb][nt][0] + bb.x) * oscale,
                                    (acc[rb][nt][1] + bb.y) * oscale);
            float2 oB = make_float2((acc[rb][nt][2] + bb.x) * oscale,
                                    (acc[rb][nt][3] + bb.y) * oscale);
            if (EPI == 2) {
                const float2 rA = *(const float2*)&res[(size_t)row0 * DD + col];
                const float2 rB = *(const float2*)&res[(size_t)(row0 + 8) * DD + col];
                oA.x += rA.x; oA.y += rA.y; oB.x += rB.x; oB.y += rB.y;
            }
            if (EPI == 1) {
                oA.x = fmaxf(oA.x, 0.f); oA.y = fmaxf(oA.y, 0.f);
                oB.x = fmaxf(oB.x, 0.f); oB.y = fmaxf(oB.y, 0.f);
            }
            if (OUTH == 0) {
                float* Y = (float*)Yv;
                *(float2*)&Y[(size_t)row0 * DD + col] = oA;
                *(float2*)&Y[(size_t)(row0 + 8) * DD + col] = oB;
            } else {
                __half* Y = (__half*)Yv;
                *(uint*)&Y[(size_t)row0 * DD + col] = h2pack(oA.x, oA.y);
                *(uint*)&Y[(size_t)(row0 + 8) * DD + col] = h2pack(oB.x, oB.y);
            }
        }
    }
}

template <int EPI, int OUTH>
__global__ void __launch_bounds__(256) gemm_kernel(
    const __half* __restrict__ X, const __half* __restrict__ Wt,
    const float* __restrict__ bias, const float* __restrict__ res,
    void* __restrict__ Y)
{
    gemm_core_h<EPI, OUTH>(X, Wt, bias, res, Y, blockIdx.y << 7, blockIdx.x << 6, 1.0f);
}

// fused QKV: grid (12, 32); writes fp16; q pre-scaled by 1/sqrt(32)
__global__ void __launch_bounds__(256) qkv_kernel(
    const __half* __restrict__ h16, const __half* __restrict__ whl,
    const float* __restrict__ bq, const float* __restrict__ bk, const float* __restrict__ bv,
    __half* __restrict__ q, __half* __restrict__ k, __half* __restrict__ v)
{
    const int sel = blockIdx.x >> 2;
    const int n0 = (blockIdx.x & 3) << 6;
    const int m0 = blockIdx.y << 7;
    const __half* Wt = whl + (size_t)sel * DD * DD;
    const float* B = (sel == 0) ? bq : (sel == 1) ? bk : bv;
    __half* Y      = (sel == 0) ? q  : (sel == 1) ? k  : v;
    const float oscale = (sel == 0) ? 0.17677669529663687f : 1.0f;
    gemm_core_h<0, 1>(h16, Wt, B, nullptr, Y, m0, n0, oscale);
}

// ============================================================================
// Flash attention: all-fp16 inputs (q pre-scaled), fp16 bias (prefetched),
// register S->P->A chaining, double-buffered K/V, key-half merge.
// ============================================================================
__global__ void __launch_bounds__(256) attn_kernel(
    const __half* __restrict__ Q, const __half* __restrict__ K,
    const __half* __restrict__ V, const __half* __restrict__ bias,
    __half* __restrict__ O)
{
    __shared__ __align__(16) __half2 Ks2[2][64][20];
    __shared__ __align__(16) __half2 Vp2[2][32][36];
    __shared__ __align__(16) float Osum[64][34];
    __shared__ float lsm[64];

    const int tid  = threadIdx.x;
    const int lane = tid & 31, warp = tid >> 5;
    const int wq = warp & 3;
    const int wn = warp >> 2;
    const int gID = lane >> 2, tig = lane & 3;
    const int q0 = blockIdx.x << 6;
    const int bh = blockIdx.y;
    const int b  = bh >> 3, h = bh & 7;
    const __half* __restrict__ bias_h = bias + ((size_t)h << 20);

    const int rowA = wq * 16 + gID;
    const int qA = q0 + rowA;

    // ---- Q fragments straight from fp16 global ----
    uint qf[2][4];
    {
        const __half* QrA = &Q[(((size_t)b * NN + qA) << 8) + (h << 5)];
        const __half* QrB = QrA + (8 << 8);
#pragma unroll
        for (int s = 0; s < 2; s++) {
            qf[s][0] = *(const uint*)&QrA[16 * s + 2 * tig];
            qf[s][1] = *(const uint*)&QrB[16 * s + 2 * tig];
            qf[s][2] = *(const uint*)&QrA[16 * s + 2 * tig + 8];
            qf[s][3] = *(const uint*)&QrB[16 * s + 2 * tig + 8];
        }
    }

    const int kr = tid >> 2, kp4 = tid & 3;     // K staging: 64 rows x 4 uint4
    const int vp = tid >> 3, dp = tid & 7;      // V staging: 32 pairs x 8 uint2

    // ---- stage K/V tile 0 ----
    {
        const uint4 kreg = *(const uint4*)&K[(((size_t)b * NN + kr) << 8) + (h << 5) + kp4 * 8];
        *(uint4*)&Ks2[0][kr][kp4 * 4] = kreg;
        const uint2 ve = *(const uint2*)&V[(((size_t)b * NN + 2 * vp) << 8) + (h << 5) + dp * 4];
        const uint2 vo = *(const uint2*)&V[(((size_t)b * NN + 2 * vp + 1) << 8) + (h << 5) + dp * 4];
        *(uint4*)&Vp2[0][vp][dp * 4] = make_uint4(
            __byte_perm(ve.x, vo.x, 0x5410), __byte_perm(ve.x, vo.x, 0x7632),
            __byte_perm(ve.y, vo.y, 0x5410), __byte_perm(ve.y, vo.y, 0x7632));
    }
    __syncthreads();

    float oacc[4][4] = {};
    float lpA = 0.f, lpB = 0.f;

#pragma unroll 1
    for (int t = 0; t < 16; t++) {
        const int cur = t & 1, nxt = cur ^ 1;

        // prefetch next K/V
        uint4 kreg; uint2 ve, vo;
        if (t < 15) {
            kreg = *(const uint4*)&K[(((size_t)b * NN + (t + 1) * 64 + kr) << 8) + (h << 5) + kp4 * 8];
            ve = *(const uint2*)&V[(((size_t)b * NN + (t + 1) * 64 + 2 * vp) << 8) + (h << 5) + dp * 4];
            vo = *(const uint2*)&V[(((size_t)b * NN + (t + 1) * 64 + 2 * vp + 1) << 8) + (h << 5) + dp * 4];
        }
        // prefetch bias (fp16) for this tile
        __half2 bbA[4], bbB[4];
        {
            const size_t bA = ((size_t)qA << 10) + t * 64 + wn * 32 + 2 * tig;
#pragma unroll
            for (int nt = 0; nt < 4; nt++) {
                bbA[nt] = *(const __half2*)&bias_h[bA + nt * 8];
                bbB[nt] = *(const __half2*)&bias_h[bA + (8 << 10) + nt * 8];
            }
        }

        // ---- QK ----
        float c4[4][4] = {};
#pragma unroll
        for (int s = 0; s < 2; s++) {
#pragma unroll
            for (int nt = 0; nt < 4; nt++) {
                const int key = wn * 32 + nt * 8 + gID;
                const uint b0 = *(const uint*)&Ks2[cur][key][8 * s + tig];
                const uint b1 = *(const uint*)&Ks2[cur][key][8 * s + 4 + tig];
                mma_f16(c4[nt], qf[s][0], qf[s][1], qf[s][2], qf[s][3], b0, b1);
            }
        }

        // ---- exp + pack P ----
        uint pa[2][4];
#pragma unroll
        for (int nt = 0; nt < 4; nt++) {
            const float2 fA = __half22float2(bbA[nt]);
            const float2 fB = __half22float2(bbB[nt]);
            const float p0 = __expf(c4[nt][0] + fA.x);
            const float p1 = __expf(c4[nt][1] + fA.y);
            const float p2 = __expf(c4[nt][2] + fB.x);
            const float p3 = __expf(c4[nt][3] + fB.y);
            lpA += p0 + p1; lpB += p2 + p3;
            const int u = nt >> 1;
            if ((nt & 1) == 0) { pa[u][0] = h2pack(p0, p1); pa[u][1] = h2pack(p2, p3); }
            else               { pa[u][2] = h2pack(p0, p1); pa[u][3] = h2pack(p2, p3); }
        }

        // ---- PV ----
#pragma unroll
        for (int u = 0; u < 2; u++) {
            const int kp = wn * 16 + u * 8 + tig;
#pragma unroll
            for (int dnt = 0; dnt < 4; dnt++) {
                const uint b0 = *(const uint*)&Vp2[cur][kp][dnt * 8 + gID];
                const uint b1 = *(const uint*)&Vp2[cur][kp + 4][dnt * 8 + gID];
                mma_f16(oacc[dnt], pa[u][0], pa[u][1], pa[u][2], pa[u][3], b0, b1);
            }
        }

        // ---- store prefetched tile ----
        if (t < 15) {
            *(uint4*)&Ks2[nxt][kr][kp4 * 4] = kreg;
            *(uint4*)&Vp2[nxt][vp][dp * 4] = make_uint4(
                __byte_perm(ve.x, vo.x, 0x5410), __byte_perm(ve.x, vo.x, 0x7632),
                __byte_perm(ve.y, vo.y, 0x5410), __byte_perm(ve.y, vo.y, 0x7632));
        }
        __syncthreads();
    }

    lpA += __shfl_xor_sync(0xffffffffu, lpA, 1);
    lpA += __shfl_xor_sync(0xffffffffu, lpA, 2);
    lpB += __shfl_xor_sync(0xffffffffu, lpB, 1);
    lpB += __shfl_xor_sync(0xffffffffu, lpB, 2);

    if (wn == 0) {
#pragma unroll
        for (int dnt = 0; dnt < 4; dnt++) {
            *(float2*)&Osum[rowA][dnt * 8 + 2 * tig] = make_float2(oacc[dnt][0], oacc[dnt][1]);
            *(float2*)&Osum[rowA + 8][dnt * 8 + 2 * tig] = make_float2(oacc[dnt][2], oacc[dnt][3]);
        }
        if (tig == 0) { lsm[rowA] = lpA; lsm[rowA + 8] = lpB; }
    }
    __syncthreads();
    if (wn == 1) {
        const float lA = 1.0f / (lsm[rowA] + lpA);
        const float lB = 1.0f / (lsm[rowA + 8] + lpB);
        const size_t oA = (((size_t)b * NN + qA) << 8) + (h << 5);
        const size_t oB = oA + (8 << 8);
#pragma unroll
        for (int dnt = 0; dnt < 4; dnt++) {
            const int col = dnt * 8 + 2 * tig;
            const float2 s0 = *(const float2*)&Osum[rowA][col];
            const float2 s1 = *(const float2*)&Osum[rowA + 8][col];
            *(uint*)&O[oA + col] = h2pack((s0.x + oacc[dnt][0]) * lA,
                                          (s0.y + oacc[dnt][1]) * lA);
            *(uint*)&O[oB + col] = h2pack((s1.x + oacc[dnt][2]) * lB,
                                          (s1.y + oacc[dnt][3]) * lB);
        }
    }
}

// ============================================================================
// LayerNorm (writes fp32 out + optional fp16 companion)
// ============================================================================
__global__ void __launch_bounds__(256) ln_kernel(
    const float* __restrict__ y, const float* __restrict__ g,
    const float* __restrict__ b, float* __restrict__ out,
    __half* __restrict__ out16)
{
    __shared__ float red[8];
    const int row = blockIdx.x, d = threadIdx.x;
    const int lane = d & 31, warp = d >> 5;
    const float v = y[(size_t)row * DD + d];

    float s = v;
#pragma unroll
    for (int off = 16; off; off >>= 1) s += __shfl_xor_sync(0xffffffffu, s, off);
    if (lane == 0) red[warp] = s;
    __syncthreads();
    float tot = red[0] + red[1] + red[2] + red[3] + red[4] + red[5] + red[6] + red[7];
    const float mu = tot * (1.0f / 256.0f);
    const float dv = v - mu;
    __syncthreads();

    float s2 = dv * dv;
#pragma unroll
    for (int off = 16; off; off >>= 1) s2 += __shfl_xor_sync(0xffffffffu, s2, off);
    if (lane == 0) red[warp] = s2;
    __syncthreads();
    float tot2 = red[0] + red[1] + red[2] + red[3] + red[4] + red[5] + red[6] + red[7];
    const float var = tot2 * (1.0f / 256.0f);

    const float o = dv * rsqrtf(var + 1e-6f) * g[d] + b[d];
    out[(size_t)row * DD + d] = o;
    if (out16) out16[(size_t)row * DD + d] = __float2half(o);
}

// ============================================================================
// host
// ============================================================================
static void* sym_addr(const void* sym) {
    void* p = nullptr;
    cudaGetSymbolAddress(&p, sym);
    return p;
}

extern "C" void kernel_launch(void* const* d_in, const int* in_sizes, int n_in,
                              void* d_out, int out_size)
{
    (void)n_in; (void)out_size;
    const float *x, *svd, *Wsvd, *bsvd, *ide, *ode, *spe;
    const float *Wq, *bq, *Wk, *bk, *Wv, *bv, *Wa, *ba, *g1, *lb1;
    const float *W1, *b1, *W2, *b2, *g2, *lb2;
    const int *ind, *outd, *spp;

    auto F = [&](int i) { return (const float*)d_in[i]; };
    auto I = [&](int i) { return (const int*)d_in[i]; };

    if (in_sizes[1] == 1024) {
        x = F(0);  ind = I(1); outd = I(2); spp = I(3);
        svd = F(4); ide = F(5); ode = F(6); spe = F(7);
        Wsvd = F(8); bsvd = F(9);
        Wq = F(10); Wk = F(11); Wv = F(12); Wa = F(13); W1 = F(14); W2 = F(15);
        bq = F(16); bk = F(17); bv = F(18); ba = F(19); b1 = F(20); b2 = F(21);
        lb1 = F(22); lb2 = F(23); g1 = F(24); g2 = F(25);
    } else {
        x = F(0); svd = F(1); Wsvd = F(2); bsvd = F(3);
        ide = F(4); ode = F(5); spe = F(6);
        Wq = F(7); bq = F(8); Wk = F(9); bk = F(10); Wv = F(11); bv = F(12);
        Wa = F(13); ba = F(14); g1 = F(15); lb1 = F(16);
        W1 = F(17); b1 = F(18); W2 = F(19); b2 = F(20); g2 = F(21); lb2 = F(22);
        ind = I(23); outd = I(24); spp = I(25);
    }

    float*  h   = (float*)sym_addr(g_h);
    __half* h16 = (__half*)sym_addr(g_h16);
    __half* qh  = (__half*)sym_addr(g_q);
    __half* kh  = (__half*)sym_addr(g_k);
    __half* vh  = (__half*)sym_addr(g_v);
    __half* oh  = (__half*)sym_addr(g_o);
    float*  y   = (float*)sym_addr(g_y);
    __half* fh  = (__half*)sym_addr(g_f);
    __half* bt  = (__half*)sym_addr(g_bias);
    __half* wh  = (__half*)sym_addr(g_wh);
    float*  out = (float*)d_out;

    const dim3 ggrid(DD / 64, MTOT / 128);    // (4, 32)
    const dim3 qgrid(12, MTOT / 128);         // fused QKV (12, 32)
    const dim3 agrid(NN / 64, BB * HH);       // (16, 32)

    whalf_kernel<<<dim3(8, 8, 24), dim3(32, 8)>>>(Wq, Wk, Wv, Wa, W1, W2, wh);
    bias_kernel<<<NN * NN / 256, 256>>>(spp, spe, bt);
    embed_kernel<<<MTOT, 256>>>(x, ind, outd, svd, Wsvd, bsvd, ide, ode, h, h16);

    for (int l = 0; l < LL; l++) {
        const __half* whl = wh + (size_t)l * 6 * DD * DD;
        const size_t bo = (size_t)l * DD;

        qkv_kernel<<<qgrid, 256>>>(h16, whl, bq + bo, bk + bo, bv + bo, qh, kh, vh);

        attn_kernel<<<agrid, 256>>>(qh, kh, vh, bt, oh);

        gemm_kernel<2, 0><<<ggrid, 256>>>(oh, whl + 3 * DD * DD, ba + bo, h, y);
        ln_kernel<<<MTOT, 256>>>(y, g1 + bo, lb1 + bo, h, h16);

        gemm_kernel<1, 1><<<ggrid, 256>>>(h16, whl + 4 * DD * DD, b1 + bo, nullptr, fh);
        gemm_kernel<2, 0><<<ggrid, 256>>>(fh, whl + 5 * DD * DD, b2 + bo, h, y);

        float* dst = (l == LL - 1) ? out : h;
        __half* dst16 = (l == LL - 1) ? nullptr : h16;
        ln_kernel<<<MTOT, 256>>>(y, g2 + bo, lb2 + bo, dst, dst16);
    }
}